// round 4
// baseline (speedup 1.0000x reference)
#include <cuda_runtime.h>
#include <cstdint>

using ull = unsigned long long;

#define GG 24
#define II 16
#define OO 16
#define SS 32768            // 32*32*32 spatial
#define NCH 384             // I*G == O*G
#define BB 2

// ---------------- device scratch (no allocations allowed) ----------------
__device__ int   g_shift[GG][GG];
__device__ int   g_rot[GG][27];
__device__ float g_Wt[NCH * NCH];      // Wt[n][k] = W[k][n], tf32-rounded
__device__ float g_TFB[NCH * 27];      // rotated depthwise taps per (o,z)
__device__ float g_y[BB * NCH * SS];   // intermediate y (100 MB)

__device__ __forceinline__ float tf32r(float f) {
    float o;
    asm("cvt.rna.tf32.f32 %0, %1;" : "=f"(o) : "f"(f));
    return o;
}
__device__ __forceinline__ uint32_t smem_u32(const void* p) {
    uint32_t a;
    asm("{ .reg .u64 t; cvta.to.shared.u64 t, %1; cvt.u32.u64 %0, t; }" : "=r"(a) : "l"(p));
    return a;
}
__device__ __forceinline__ void mma_tf32(float* c, const uint32_t* a, uint32_t b0, uint32_t b1) {
    asm volatile(
        "mma.sync.aligned.m16n8k8.row.col.f32.tf32.tf32.f32 "
        "{%0,%1,%2,%3}, {%4,%5,%6,%7}, {%8,%9}, {%0,%1,%2,%3};"
        : "+f"(c[0]), "+f"(c[1]), "+f"(c[2]), "+f"(c[3])
        : "r"(a[0]), "r"(a[1]), "r"(a[2]), "r"(a[3]), "r"(b0), "r"(b1));
}
// ---- packed f32x2 helpers ----
__device__ __forceinline__ ull ffma2(ull a, ull b, ull c) {
    ull d;
    asm("fma.rn.f32x2 %0, %1, %2, %3;" : "=l"(d) : "l"(a), "l"(b), "l"(c));
    return d;
}
__device__ __forceinline__ ull dup2(float f) {
    ull d;
    asm("mov.b64 %0, {%1, %1};" : "=l"(d) : "f"(f));
    return d;
}
__device__ __forceinline__ ull pk2(float lo, float hi) {
    ull d;
    asm("mov.b64 %0, {%1, %2};" : "=l"(d) : "f"(lo), "f"(hi));
    return d;
}
__device__ __forceinline__ float2 unpack2(ull u) {
    float2 r;
    asm("mov.b64 {%0, %1}, %2;" : "=f"(r.x), "=f"(r.y) : "l"(u));
    return r;
}

// ---------------- table construction (replicates numpy enumeration) -----
__global__ void build_tables_kernel() {
    __shared__ int mats[24][9];
    int tid = threadIdx.x;
    if (tid == 0) {
        const int perms[6][3] = {{0,1,2},{0,2,1},{1,0,2},{1,2,0},{2,0,1},{2,1,0}};
        int cnt = 0;
        for (int p = 0; p < 6; p++)
            for (int sb = 0; sb < 8; sb++) {
                int s0 = (sb & 4) ? -1 : 1, s1 = (sb & 2) ? -1 : 1, s2 = (sb & 1) ? -1 : 1;
                int M[9] = {0,0,0,0,0,0,0,0,0};
                M[0*3 + perms[p][0]] = s0;
                M[1*3 + perms[p][1]] = s1;
                M[2*3 + perms[p][2]] = s2;
                int det = M[0]*(M[4]*M[8]-M[5]*M[7]) - M[1]*(M[3]*M[8]-M[5]*M[6]) + M[2]*(M[3]*M[7]-M[4]*M[6]);
                if (det == 1) { for (int q = 0; q < 9; q++) mats[cnt][q] = M[q]; cnt++; }
            }
    }
    __syncthreads();
    if (tid < 576) {                       // shift[g][h] = idx(Rg^T * Rh)
        int g = tid / 24, h = tid % 24;
        int R[9];
        for (int a = 0; a < 3; a++)
            for (int b = 0; b < 3; b++) {
                int v = 0;
                for (int c = 0; c < 3; c++) v += mats[g][c*3+a] * mats[h][c*3+b];
                R[a*3+b] = v;
            }
        int idx = 0;
        for (int j = 0; j < 24; j++) {
            bool eq = true;
            for (int q = 0; q < 9; q++) if (mats[j][q] != R[q]) { eq = false; break; }
            if (eq) { idx = j; break; }
        }
        g_shift[g][h] = idx;
    }
    if (tid < 648) {                       // rot_idx[g][j]
        int g = tid / 27, j = tid % 27;
        int x0 = j / 9 - 1, x1 = (j / 3) % 3 - 1, x2 = j % 3 - 1;
        int r0 = x0*mats[g][0] + x1*mats[g][3] + x2*mats[g][6] + 1;
        int r1 = x0*mats[g][1] + x1*mats[g][4] + x2*mats[g][7] + 1;
        int r2 = x0*mats[g][2] + x1*mats[g][5] + x2*mats[g][8] + 1;
        g_rot[g][j] = r0*9 + r1*3 + r2;
    }
}

__global__ void build_wt_kernel(const float* __restrict__ gw) {
    int idx = blockIdx.x * blockDim.x + threadIdx.x;
    if (idx >= NCH * NCH) return;
    int n = idx / NCH, k = idx % NCH;
    int o = n / GG, z = n % GG;
    int i = k / GG, g = k % GG;
    g_Wt[idx] = tf32r(gw[(g_shift[z][g] * OO + o) * II + i]);
}

__global__ void build_tfb_kernel(const float* __restrict__ tw) {
    int idx = blockIdx.x * blockDim.x + threadIdx.x;
    if (idx >= NCH * 27) return;
    int n = idx / 27, j = idx % 27;
    g_TFB[idx] = tw[(n / GG) * 27 + g_rot[n % GG][j]];
}

// ================= tf32 mma.sync GEMM (ldmatrix + vector B) =================
// C[n][m] = sum_k Wt[n][k] * x[k][m]; CTA 128n x 128m, k-stage 16, 4 warps 2x2,
// warp tile 64n x 64m. A frags via ldmatrix.x4 (pitch 20). B: logical mma-n j
// maps to m = wc*64 + ni + 8*j so each lane's 8 B values per k-row are one
// float4 pair. Epilogue transposes C through per-warp smem for coalesced STG.
__global__ void __launch_bounds__(128)
gemm_mma_kernel(const float* __restrict__ x, const float* __restrict__ gbias) {
    __shared__ float As[2][128][20];
    __shared__ float Bs[2][16][132];
    __shared__ float Tsm[4][16][68];

    const int tid  = threadIdx.x;
    const int lane = tid & 31;
    const int wid  = tid >> 5;
    const int wr   = wid >> 1;
    const int wc   = wid & 1;
    const int n0   = blockIdx.x * 128;    // 0,128,256
    const int m0   = blockIdx.y * 128;
    const int b    = m0 >> 15;
    const int ms   = m0 & (SS - 1);

    const int gid  = lane >> 2;
    const int tig  = lane & 3;

    float acc[4][8][4];
    #pragma unroll
    for (int i = 0; i < 4; i++)
        #pragma unroll
        for (int j = 0; j < 8; j++)
            #pragma unroll
            for (int q = 0; q < 4; q++) acc[i][j][q] = 0.0f;

    // ldmatrix per-lane address base: lanes 0-7 -> rows R+0..7 col kk,
    // 8-15 -> rows R+0..7 col kk+4, 16-23 -> rows R+8..15 col kk, 24-31 -> +4
    const int row_extra = ((lane >> 4) & 1) * 8 + (lane & 7);
    const int col_extra = ((lane >> 3) & 1) * 4;
    const uint32_t aldm = smem_u32(&As[0][wr * 64 + row_extra][col_extra]);

    float4 ra[4], rb[4];
    auto ldg_stage = [&](int kt) {
        const int k0 = kt * 16;
        #pragma unroll
        for (int it = 0; it < 4; it++) {
            int v = tid + it * 128;
            int arow = v >> 2, ac4 = (v & 3) << 2;
            ra[it] = *(const float4*)&g_Wt[(n0 + arow) * NCH + k0 + ac4];
            int brow = v >> 5, bc4 = (v & 31) << 2;
            rb[it] = *(const float4*)&x[(((size_t)(b * NCH + k0 + brow)) << 15) + ms + bc4];
        }
    };
    auto sts_stage = [&](int s) {
        #pragma unroll
        for (int it = 0; it < 4; it++) {
            int v = tid + it * 128;
            int arow = v >> 2, ac4 = (v & 3) << 2;
            *(float4*)&As[s][arow][ac4] = ra[it];
            int brow = v >> 5, bc4 = (v & 31) << 2;
            float4 t = rb[it];
            t.x = tf32r(t.x); t.y = tf32r(t.y); t.z = tf32r(t.z); t.w = tf32r(t.w);
            *(float4*)&Bs[s][brow][bc4] = t;
        }
    };

    ldg_stage(0);
    sts_stage(0);
    __syncthreads();

    for (int kt = 0; kt < 24; kt++) {
        const int cur = kt & 1;
        if (kt < 23) ldg_stage(kt + 1);

        #pragma unroll
        for (int ks = 0; ks < 2; ks++) {
            uint32_t af[4][4];
            #pragma unroll
            for (int mi = 0; mi < 4; mi++) {
                uint32_t r0, r1, r2, r3;
                uint32_t addr = aldm + (uint32_t)(cur * 10240 + mi * 1280 + ks * 32);
                asm volatile("ldmatrix.sync.aligned.m8n8.x4.shared.b16 {%0,%1,%2,%3}, [%4];"
                             : "=r"(r0), "=r"(r1), "=r"(r2), "=r"(r3) : "r"(addr));
                af[mi][0] = r0; af[mi][1] = r2; af[mi][2] = r1; af[mi][3] = r3;
            }
            const float* bp = &Bs[cur][ks * 8 + tig][wc * 64 + 8 * gid];
            float4 q0a = *(const float4*)bp;
            float4 q0b = *(const float4*)(bp + 4);
            float4 q1a = *(const float4*)(bp + 4 * 132);
            float4 q1b = *(const float4*)(bp + 4 * 132 + 4);
            uint32_t B0[8] = {__float_as_uint(q0a.x), __float_as_uint(q0a.y),
                              __float_as_uint(q0a.z), __float_as_uint(q0a.w),
                              __float_as_uint(q0b.x), __float_as_uint(q0b.y),
                              __float_as_uint(q0b.z), __float_as_uint(q0b.w)};
            uint32_t B1[8] = {__float_as_uint(q1a.x), __float_as_uint(q1a.y),
                              __float_as_uint(q1a.z), __float_as_uint(q1a.w),
                              __float_as_uint(q1b.x), __float_as_uint(q1b.y),
                              __float_as_uint(q1b.z), __float_as_uint(q1b.w)};
            #pragma unroll
            for (int mi = 0; mi < 4; mi++)
                #pragma unroll
                for (int ni = 0; ni < 8; ni++)
                    mma_tf32(acc[mi][ni], af[mi], B0[ni], B1[ni]);
        }

        if (kt < 23) sts_stage((kt + 1) & 1);
        __syncthreads();
    }

    // ---- epilogue: transpose through per-warp smem, coalesced stores ----
    #pragma unroll 1
    for (int mi = 0; mi < 4; mi++) {
        const int nb = n0 + wr * 64 + mi * 16;
        const float blo = gbias[(nb + gid) / GG];
        const float bhi = gbias[(nb + gid + 8) / GG];
        #pragma unroll
        for (int ni = 0; ni < 8; ni++) {
            int mL = ni + 16 * tig;
            Tsm[wid][gid][mL]         = acc[mi][ni][0] + blo;
            Tsm[wid][gid][mL + 8]     = acc[mi][ni][1] + blo;
            Tsm[wid][gid + 8][mL]     = acc[mi][ni][2] + bhi;
            Tsm[wid][gid + 8][mL + 8] = acc[mi][ni][3] + bhi;
        }
        __syncwarp();
        #pragma unroll
        for (int rr = 0; rr < 8; rr++) {
            int row = (lane >> 4) + rr * 2;
            int chunk = lane & 15;
            float4 v = *(const float4*)&Tsm[wid][row][chunk * 4];
            *(float4*)&g_y[(((size_t)(b * NCH + nb + row)) << 15) + ms + wc * 64 + chunk * 4] = v;
        }
        __syncwarp();
    }
}

// ================= depthwise 3x3x3 conv + bias + leaky ReLU (f32x2) =========
// CTA = channel x 8-h slab. Each thread: 8 outputs along d as 4 packed pairs.
__global__ void __launch_bounds__(256)
conv_kernel(float* __restrict__ out, const float* __restrict__ tbias) {
    __shared__ float tile[10][34][34];
    __shared__ float2 tap2[27];
    __shared__ float sbias;

    const int ch = blockIdx.x >> 2;
    const int h0 = (blockIdx.x & 3) * 8;
    const int tid = threadIdx.x;

    const float* ybase = g_y + (size_t)ch * SS;
    if (tid < 27) {
        float t = g_TFB[(ch % NCH) * 27 + tid];
        tap2[tid] = make_float2(t, t);
    }
    if (tid == 27) sbias = tbias[0];

    for (int idx = tid; idx < 10 * 34 * 34; idx += 256) {
        int hh = idx / 1156;
        int r  = idx - hh * 1156;
        int ww = r / 34;
        int td = r - ww * 34;
        int gh = h0 + hh - 1, gw_ = ww - 1, gd = td - 1;
        float v = 0.0f;
        if (gh >= 0 && gh < 32 && gw_ >= 0 && gw_ < 32 && gd >= 0 && gd < 32)
            v = ybase[(gh * 32 + gw_) * 32 + gd];
        tile[hh][ww][td] = v;
    }
    __syncthreads();

    float* obase = out + (size_t)ch * SS + (size_t)h0 * 1024;
    #pragma unroll 1
    for (int it = 0; it < 4; it++) {
        int q = tid + it * 256;          // 0..1023
        int d0 = (q & 3) << 3;           // 0,8,16,24
        int w = (q >> 2) & 31;
        int h = q >> 7;
        ull a0 = dup2(sbias), a1 = a0, a2 = a0, a3 = a0;
        #pragma unroll
        for (int a = 0; a < 3; a++)
            #pragma unroll
            for (int bq = 0; bq < 3; bq++) {
                const float* rp = &tile[h + a][w + bq][d0];
                float2 f0 = *(const float2*)(rp + 0);
                float2 f1 = *(const float2*)(rp + 2);
                float2 f2 = *(const float2*)(rp + 4);
                float2 f3 = *(const float2*)(rp + 6);
                float2 f4 = *(const float2*)(rp + 8);
                ull w0 = pk2(f0.x, f0.y), w1 = pk2(f1.x, f1.y), w2 = pk2(f2.x, f2.y);
                ull w3 = pk2(f3.x, f3.y), w4 = pk2(f4.x, f4.y);
                ull s0 = pk2(f0.y, f1.x), s1 = pk2(f1.y, f2.x);
                ull s2 = pk2(f2.y, f3.x), s3 = pk2(f3.y, f4.x);
                const ull* tp = (const ull*)&tap2[a * 9 + bq * 3];
                ull t0 = tp[0], t1 = tp[1], t2 = tp[2];
                a0 = ffma2(t0, w0, a0); a0 = ffma2(t1, s0, a0); a0 = ffma2(t2, w1, a0);
                a1 = ffma2(t0, w1, a1); a1 = ffma2(t1, s1, a1); a1 = ffma2(t2, w2, a1);
                a2 = ffma2(t0, w2, a2); a2 = ffma2(t1, s2, a2); a2 = ffma2(t2, w3, a2);
                a3 = ffma2(t0, w3, a3); a3 = ffma2(t1, s3, a3); a3 = ffma2(t2, w4, a3);
            }
        float2 u0 = unpack2(a0), u1 = unpack2(a1), u2 = unpack2(a2), u3 = unpack2(a3);
        float4 o0, o1;
        o0.x = u0.x > 0.0f ? u0.x : 0.01f * u0.x;
        o0.y = u0.y > 0.0f ? u0.y : 0.01f * u0.y;
        o0.z = u1.x > 0.0f ? u1.x : 0.01f * u1.x;
        o0.w = u1.y > 0.0f ? u1.y : 0.01f * u1.y;
        o1.x = u2.x > 0.0f ? u2.x : 0.01f * u2.x;
        o1.y = u2.y > 0.0f ? u2.y : 0.01f * u2.y;
        o1.z = u3.x > 0.0f ? u3.x : 0.01f * u3.x;
        o1.w = u3.y > 0.0f ? u3.y : 0.01f * u3.y;
        float* dst = obase + ((h * 32 + w) * 32 + d0);
        *(float4*)dst = o0;
        *(float4*)(dst + 4) = o1;
    }
}

// ---------------- launch ----------------
extern "C" void kernel_launch(void* const* d_in, const int* in_sizes, int n_in,
                              void* d_out, int out_size) {
    const float* x  = (const float*)d_in[0];
    const float* gw = (const float*)d_in[1];
    const float* tw = (const float*)d_in[2];
    const float* gb = (const float*)d_in[3];
    const float* tb = (const float*)d_in[4];
    float* out = (float*)d_out;

    build_tables_kernel<<<1, 648>>>();
    build_wt_kernel<<<(NCH * NCH + 255) / 256, 256>>>(gw);
    build_tfb_kernel<<<(NCH * 27 + 255) / 256, 256>>>(tw);

    dim3 gg(3, 512);      // x = n-tile fastest: CTAs sharing an m-stripe co-scheduled
    gemm_mma_kernel<<<gg, 128>>>(x, gb);
    conv_kernel<<<3072, 256>>>(out, tb);
}

// round 5
// speedup vs baseline: 3.4629x; 3.4629x over previous
#include <cuda_runtime.h>
#include <cstdint>

using ull = unsigned long long;

#define GG 24
#define II 16
#define OO 16
#define SS 32768            // 32*32*32 spatial
#define NCH 384             // I*G == O*G
#define BB 2

// ---------------- device scratch (no allocations allowed) ----------------
__device__ int   g_shift[GG][GG];
__device__ int   g_rot[GG][27];
__device__ float g_Wt[NCH * NCH];      // Wt[n][k] = W[k][n], tf32-rounded (RNA)
__device__ float g_TFB[NCH * 27];      // rotated depthwise taps per (o,z)
__device__ float g_y[BB * NCH * SS];   // intermediate y (100 MB)

__device__ __forceinline__ float tf32r(float f) {
    float o;
    asm("cvt.rna.tf32.f32 %0, %1;" : "=f"(o) : "f"(f));
    return o;
}
__device__ __forceinline__ uint32_t smem_u32(const void* p) {
    uint32_t a;
    asm("{ .reg .u64 t; cvta.to.shared.u64 t, %1; cvt.u32.u64 %0, t; }" : "=r"(a) : "l"(p));
    return a;
}
__device__ __forceinline__ void mma_tf32(float* c, const uint32_t* a, uint32_t b0, uint32_t b1) {
    asm volatile(
        "mma.sync.aligned.m16n8k8.row.col.f32.tf32.tf32.f32 "
        "{%0,%1,%2,%3}, {%4,%5,%6,%7}, {%8,%9}, {%0,%1,%2,%3};"
        : "+f"(c[0]), "+f"(c[1]), "+f"(c[2]), "+f"(c[3])
        : "r"(a[0]), "r"(a[1]), "r"(a[2]), "r"(a[3]), "r"(b0), "r"(b1));
}
__device__ __forceinline__ void cpasync16(uint32_t dst, const void* src) {
    asm volatile("cp.async.cg.shared.global [%0], [%1], 16;" :: "r"(dst), "l"(src));
}
#define CP_COMMIT() asm volatile("cp.async.commit_group;" ::: "memory")
#define CP_WAIT(n)  asm volatile("cp.async.wait_group %0;" :: "n"(n) : "memory")

// ---- packed f32x2 helpers (conv) ----
__device__ __forceinline__ ull ffma2(ull a, ull b, ull c) {
    ull d;
    asm("fma.rn.f32x2 %0, %1, %2, %3;" : "=l"(d) : "l"(a), "l"(b), "l"(c));
    return d;
}
__device__ __forceinline__ ull dup2(float f) {
    ull d;
    asm("mov.b64 %0, {%1, %1};" : "=l"(d) : "f"(f));
    return d;
}
__device__ __forceinline__ ull pk2(float lo, float hi) {
    ull d;
    asm("mov.b64 %0, {%1, %2};" : "=l"(d) : "f"(lo), "f"(hi));
    return d;
}
__device__ __forceinline__ float2 unpack2(ull u) {
    float2 r;
    asm("mov.b64 {%0, %1}, %2;" : "=f"(r.x), "=f"(r.y) : "l"(u));
    return r;
}

// ---------------- table construction (replicates numpy enumeration) -----
__global__ void build_tables_kernel() {
    __shared__ int mats[24][9];
    int tid = threadIdx.x;
    if (tid == 0) {
        const int perms[6][3] = {{0,1,2},{0,2,1},{1,0,2},{1,2,0},{2,0,1},{2,1,0}};
        int cnt = 0;
        for (int p = 0; p < 6; p++)
            for (int sb = 0; sb < 8; sb++) {
                int s0 = (sb & 4) ? -1 : 1, s1 = (sb & 2) ? -1 : 1, s2 = (sb & 1) ? -1 : 1;
                int M[9] = {0,0,0,0,0,0,0,0,0};
                M[0*3 + perms[p][0]] = s0;
                M[1*3 + perms[p][1]] = s1;
                M[2*3 + perms[p][2]] = s2;
                int det = M[0]*(M[4]*M[8]-M[5]*M[7]) - M[1]*(M[3]*M[8]-M[5]*M[6]) + M[2]*(M[3]*M[7]-M[4]*M[6]);
                if (det == 1) { for (int q = 0; q < 9; q++) mats[cnt][q] = M[q]; cnt++; }
            }
    }
    __syncthreads();
    if (tid < 576) {                       // shift[g][h] = idx(Rg^T * Rh)
        int g = tid / 24, h = tid % 24;
        int R[9];
        for (int a = 0; a < 3; a++)
            for (int b = 0; b < 3; b++) {
                int v = 0;
                for (int c = 0; c < 3; c++) v += mats[g][c*3+a] * mats[h][c*3+b];
                R[a*3+b] = v;
            }
        int idx = 0;
        for (int j = 0; j < 24; j++) {
            bool eq = true;
            for (int q = 0; q < 9; q++) if (mats[j][q] != R[q]) { eq = false; break; }
            if (eq) { idx = j; break; }
        }
        g_shift[g][h] = idx;
    }
    if (tid < 648) {                       // rot_idx[g][j]
        int g = tid / 27, j = tid % 27;
        int x0 = j / 9 - 1, x1 = (j / 3) % 3 - 1, x2 = j % 3 - 1;
        int r0 = x0*mats[g][0] + x1*mats[g][3] + x2*mats[g][6] + 1;
        int r1 = x0*mats[g][1] + x1*mats[g][4] + x2*mats[g][7] + 1;
        int r2 = x0*mats[g][2] + x1*mats[g][5] + x2*mats[g][8] + 1;
        g_rot[g][j] = r0*9 + r1*3 + r2;
    }
}

__global__ void build_wt_kernel(const float* __restrict__ gw) {
    int idx = blockIdx.x * blockDim.x + threadIdx.x;
    if (idx >= NCH * NCH) return;
    int n = idx / NCH, k = idx % NCH;
    int o = n / GG, z = n % GG;
    int i = k / GG, g = k % GG;
    g_Wt[idx] = tf32r(gw[(g_shift[z][g] * OO + o) * II + i]);
}

__global__ void build_tfb_kernel(const float* __restrict__ tw) {
    int idx = blockIdx.x * blockDim.x + threadIdx.x;
    if (idx >= NCH * 27) return;
    int n = idx / 27, j = idx % 27;
    g_TFB[idx] = tw[(n / GG) * 27 + g_rot[n % GG][j]];
}

// ================= tf32 mma.sync GEMM, cp.async 2-stage =================
// C[n][m] = sum_k Wt[n][k] * x[k][m]; CTA 128n x 128m, k-stage 16.
// 256 threads = 8 warps (2 n-halves x 4 m-quarters); warp tile 64n x 32m.
// A smem [n][k] pitch 20 (conflict-free frag reads + ldst), B smem [k][m]
// pitch 136 (conflict-free). x tf32-rounded at B-fragment load (RNA).
__global__ void __launch_bounds__(256, 2)
gemm_mma_kernel(const float* __restrict__ x, const float* __restrict__ gbias) {
    __shared__ float As[2][128][20];
    __shared__ float Bs[2][16][136];

    const int tid  = threadIdx.x;
    const int lane = tid & 31;
    const int wid  = tid >> 5;
    const int wr   = wid >> 2;            // 0..1 : n 64-half
    const int wc   = wid & 3;             // 0..3 : m 32-quarter
    const int n0   = blockIdx.x * 128;    // 0,128,256
    const int m0   = blockIdx.y * 128;
    const int b    = m0 >> 15;
    const int ms   = m0 & (SS - 1);

    const int gid  = lane >> 2;           // 0..7
    const int tig  = lane & 3;            // 0..3

    float acc[4][4][4];
    #pragma unroll
    for (int i = 0; i < 4; i++)
        #pragma unroll
        for (int j = 0; j < 4; j++)
            #pragma unroll
            for (int q = 0; q < 4; q++) acc[i][j][q] = 0.0f;

    // per-thread cp.async slots (2 A + 2 B per stage)
    const int ar0 = tid >> 2,  ac0 = (tid & 3) << 2;          // A slot 0
    const int ar1 = ar0 + 64;                                  // A slot 1 (tid+256)
    const int br0 = tid >> 5,  bc0 = (tid & 31) << 2;         // B slot 0
    const int br1 = br0 + 8;                                   // B slot 1

    auto prefetch = [&](int kt, int s) {
        const int k0 = kt * 16;
        cpasync16(smem_u32(&As[s][ar0][ac0]), &g_Wt[(n0 + ar0) * NCH + k0 + ac0]);
        cpasync16(smem_u32(&As[s][ar1][ac0]), &g_Wt[(n0 + ar1) * NCH + k0 + ac0]);
        cpasync16(smem_u32(&Bs[s][br0][bc0]), &x[(((size_t)(b * NCH + k0 + br0)) << 15) + ms + bc0]);
        cpasync16(smem_u32(&Bs[s][br1][bc0]), &x[(((size_t)(b * NCH + k0 + br1)) << 15) + ms + bc0]);
    };

    prefetch(0, 0);
    CP_COMMIT();

    for (int kt = 0; kt < 24; kt++) {
        const int cur = kt & 1;
        if (kt < 23) {
            prefetch(kt + 1, cur ^ 1);
            CP_COMMIT();
            CP_WAIT(1);
        } else {
            CP_WAIT(0);
        }
        __syncthreads();

        #pragma unroll
        for (int ks = 0; ks < 2; ks++) {
            const int kk = ks * 8;
            uint32_t af[4][4];
            #pragma unroll
            for (int mi = 0; mi < 4; mi++) {
                int row = wr * 64 + mi * 16 + gid;
                af[mi][0] = __float_as_uint(As[cur][row][kk + tig]);
                af[mi][1] = __float_as_uint(As[cur][row + 8][kk + tig]);
                af[mi][2] = __float_as_uint(As[cur][row][kk + tig + 4]);
                af[mi][3] = __float_as_uint(As[cur][row + 8][kk + tig + 4]);
            }
            uint32_t bf[4][2];
            #pragma unroll
            for (int ni = 0; ni < 4; ni++) {
                int m = wc * 32 + ni * 8 + gid;
                bf[ni][0] = __float_as_uint(tf32r(Bs[cur][kk + tig][m]));
                bf[ni][1] = __float_as_uint(tf32r(Bs[cur][kk + tig + 4][m]));
            }
            #pragma unroll
            for (int mi = 0; mi < 4; mi++)
                #pragma unroll
                for (int ni = 0; ni < 4; ni++)
                    mma_tf32(acc[mi][ni], af[mi], bf[ni][0], bf[ni][1]);
        }
        __syncthreads();
    }

    // epilogue: add bias, direct float2 stores (proven R3 layout)
    #pragma unroll
    for (int mi = 0; mi < 4; mi++) {
        int nlo = n0 + wr * 64 + mi * 16 + gid;
        float blo = gbias[nlo / GG];
        float bhi = gbias[(nlo + 8) / GG];
        float* rowlo = &g_y[(((size_t)(b * NCH + nlo)) << 15) + ms];
        float* rowhi = rowlo + ((size_t)8 << 15);
        #pragma unroll
        for (int ni = 0; ni < 4; ni++) {
            int m = wc * 32 + ni * 8 + tig * 2;
            float2 lo = make_float2(acc[mi][ni][0] + blo, acc[mi][ni][1] + blo);
            float2 hi = make_float2(acc[mi][ni][2] + bhi, acc[mi][ni][3] + bhi);
            *(float2*)(rowlo + m) = lo;
            *(float2*)(rowhi + m) = hi;
        }
    }
}

// ================= depthwise 3x3x3 conv + bias + leaky ReLU (f32x2) =========
__global__ void __launch_bounds__(256)
conv_kernel(float* __restrict__ out, const float* __restrict__ tbias) {
    __shared__ float tile[10][34][34];
    __shared__ float2 tap2[27];
    __shared__ float sbias;

    const int ch = blockIdx.x >> 2;
    const int h0 = (blockIdx.x & 3) * 8;
    const int tid = threadIdx.x;

    const float* ybase = g_y + (size_t)ch * SS;
    if (tid < 27) {
        float t = g_TFB[(ch % NCH) * 27 + tid];
        tap2[tid] = make_float2(t, t);
    }
    if (tid == 27) sbias = tbias[0];

    for (int idx = tid; idx < 10 * 34 * 34; idx += 256) {
        int hh = idx / 1156;
        int r  = idx - hh * 1156;
        int ww = r / 34;
        int td = r - ww * 34;
        int gh = h0 + hh - 1, gw_ = ww - 1, gd = td - 1;
        float v = 0.0f;
        if (gh >= 0 && gh < 32 && gw_ >= 0 && gw_ < 32 && gd >= 0 && gd < 32)
            v = ybase[(gh * 32 + gw_) * 32 + gd];
        tile[hh][ww][td] = v;
    }
    __syncthreads();

    float* obase = out + (size_t)ch * SS + (size_t)h0 * 1024;
    #pragma unroll 1
    for (int it = 0; it < 4; it++) {
        int q = tid + it * 256;          // 0..1023
        int d0 = (q & 3) << 3;           // 0,8,16,24
        int w = (q >> 2) & 31;
        int h = q >> 7;
        ull a0 = dup2(sbias), a1 = a0, a2 = a0, a3 = a0;
        #pragma unroll
        for (int a = 0; a < 3; a++)
            #pragma unroll
            for (int bq = 0; bq < 3; bq++) {
                const float* rp = &tile[h + a][w + bq][d0];
                float2 f0 = *(const float2*)(rp + 0);
                float2 f1 = *(const float2*)(rp + 2);
                float2 f2 = *(const float2*)(rp + 4);
                float2 f3 = *(const float2*)(rp + 6);
                float2 f4 = *(const float2*)(rp + 8);
                ull w0 = pk2(f0.x, f0.y), w1 = pk2(f1.x, f1.y), w2 = pk2(f2.x, f2.y);
                ull w3 = pk2(f3.x, f3.y), w4 = pk2(f4.x, f4.y);
                ull s0 = pk2(f0.y, f1.x), s1 = pk2(f1.y, f2.x);
                ull s2 = pk2(f2.y, f3.x), s3 = pk2(f3.y, f4.x);
                const ull* tp = (const ull*)&tap2[a * 9 + bq * 3];
                ull t0 = tp[0], t1 = tp[1], t2 = tp[2];
                a0 = ffma2(t0, w0, a0); a0 = ffma2(t1, s0, a0); a0 = ffma2(t2, w1, a0);
                a1 = ffma2(t0, w1, a1); a1 = ffma2(t1, s1, a1); a1 = ffma2(t2, w2, a1);
                a2 = ffma2(t0, w2, a2); a2 = ffma2(t1, s2, a2); a2 = ffma2(t2, w3, a2);
                a3 = ffma2(t0, w3, a3); a3 = ffma2(t1, s3, a3); a3 = ffma2(t2, w4, a3);
            }
        float2 u0 = unpack2(a0), u1 = unpack2(a1), u2 = unpack2(a2), u3 = unpack2(a3);
        float4 o0, o1;
        o0.x = u0.x > 0.0f ? u0.x : 0.01f * u0.x;
        o0.y = u0.y > 0.0f ? u0.y : 0.01f * u0.y;
        o0.z = u1.x > 0.0f ? u1.x : 0.01f * u1.x;
        o0.w = u1.y > 0.0f ? u1.y : 0.01f * u1.y;
        o1.x = u2.x > 0.0f ? u2.x : 0.01f * u2.x;
        o1.y = u2.y > 0.0f ? u2.y : 0.01f * u2.y;
        o1.z = u3.x > 0.0f ? u3.x : 0.01f * u3.x;
        o1.w = u3.y > 0.0f ? u3.y : 0.01f * u3.y;
        float* dst = obase + ((h * 32 + w) * 32 + d0);
        *(float4*)dst = o0;
        *(float4*)(dst + 4) = o1;
    }
}

// ---------------- launch ----------------
extern "C" void kernel_launch(void* const* d_in, const int* in_sizes, int n_in,
                              void* d_out, int out_size) {
    const float* x  = (const float*)d_in[0];
    const float* gw = (const float*)d_in[1];
    const float* tw = (const float*)d_in[2];
    const float* gb = (const float*)d_in[3];
    const float* tb = (const float*)d_in[4];
    float* out = (float*)d_out;

    build_tables_kernel<<<1, 648>>>();
    build_wt_kernel<<<(NCH * NCH + 255) / 256, 256>>>(gw);
    build_tfb_kernel<<<(NCH * 27 + 255) / 256, 256>>>(tw);

    dim3 gg(3, 512);      // x = n-tile fastest: CTAs sharing an m-stripe co-scheduled
    gemm_mma_kernel<<<gg, 256>>>(x, gb);
    conv_kernel<<<3072, 256>>>(out, tb);
}

// round 6
// speedup vs baseline: 3.9643x; 1.1448x over previous
#include <cuda_runtime.h>
#include <cstdint>

using ull = unsigned long long;

#define GG 24
#define II 16
#define OO 16
#define SS 32768            // 32*32*32 spatial
#define NCH 384             // I*G == O*G
#define BB 2

// ---------------- device scratch (no allocations allowed) ----------------
__device__ int   g_shift[GG][GG];
__device__ int   g_rot[GG][27];
__device__ float g_Wt[NCH * NCH];      // Wt[n][k] = W[k][n], tf32-rounded (RNA)
__device__ float g_TFB[NCH * 27];      // rotated depthwise taps per (o,z)
__device__ float g_y[BB * NCH * SS];   // intermediate y (100 MB)

__device__ __forceinline__ float tf32r(float f) {
    float o;
    asm("cvt.rna.tf32.f32 %0, %1;" : "=f"(o) : "f"(f));
    return o;
}
__device__ __forceinline__ uint32_t smem_u32(const void* p) {
    uint32_t a;
    asm("{ .reg .u64 t; cvta.to.shared.u64 t, %1; cvt.u32.u64 %0, t; }" : "=r"(a) : "l"(p));
    return a;
}
__device__ __forceinline__ void mma_tf32(float* c, const uint32_t* a, uint32_t b0, uint32_t b1) {
    asm volatile(
        "mma.sync.aligned.m16n8k8.row.col.f32.tf32.tf32.f32 "
        "{%0,%1,%2,%3}, {%4,%5,%6,%7}, {%8,%9}, {%0,%1,%2,%3};"
        : "+f"(c[0]), "+f"(c[1]), "+f"(c[2]), "+f"(c[3])
        : "r"(a[0]), "r"(a[1]), "r"(a[2]), "r"(a[3]), "r"(b0), "r"(b1));
}
__device__ __forceinline__ void cpasync16(uint32_t dst, const void* src) {
    asm volatile("cp.async.cg.shared.global [%0], [%1], 16;" :: "r"(dst), "l"(src));
}
#define CP_COMMIT() asm volatile("cp.async.commit_group;" ::: "memory")
#define CP_WAIT(n)  asm volatile("cp.async.wait_group %0;" :: "n"(n) : "memory")

// ---- packed f32x2 helpers (conv) ----
__device__ __forceinline__ ull ffma2(ull a, ull b, ull c) {
    ull d;
    asm("fma.rn.f32x2 %0, %1, %2, %3;" : "=l"(d) : "l"(a), "l"(b), "l"(c));
    return d;
}
__device__ __forceinline__ ull dup2(float f) {
    ull d;
    asm("mov.b64 %0, {%1, %1};" : "=l"(d) : "f"(f));
    return d;
}
__device__ __forceinline__ ull pk2(float lo, float hi) {
    ull d;
    asm("mov.b64 %0, {%1, %2};" : "=l"(d) : "f"(lo), "f"(hi));
    return d;
}
__device__ __forceinline__ float2 unpack2(ull u) {
    float2 r;
    asm("mov.b64 {%0, %1}, %2;" : "=f"(r.x), "=f"(r.y) : "l"(u));
    return r;
}

// ---------------- table construction (replicates numpy enumeration) -----
__global__ void build_tables_kernel() {
    __shared__ int mats[24][9];
    int tid = threadIdx.x;
    if (tid == 0) {
        const int perms[6][3] = {{0,1,2},{0,2,1},{1,0,2},{1,2,0},{2,0,1},{2,1,0}};
        int cnt = 0;
        for (int p = 0; p < 6; p++)
            for (int sb = 0; sb < 8; sb++) {
                int s0 = (sb & 4) ? -1 : 1, s1 = (sb & 2) ? -1 : 1, s2 = (sb & 1) ? -1 : 1;
                int M[9] = {0,0,0,0,0,0,0,0,0};
                M[0*3 + perms[p][0]] = s0;
                M[1*3 + perms[p][1]] = s1;
                M[2*3 + perms[p][2]] = s2;
                int det = M[0]*(M[4]*M[8]-M[5]*M[7]) - M[1]*(M[3]*M[8]-M[5]*M[6]) + M[2]*(M[3]*M[7]-M[4]*M[6]);
                if (det == 1) { for (int q = 0; q < 9; q++) mats[cnt][q] = M[q]; cnt++; }
            }
    }
    __syncthreads();
    if (tid < 576) {                       // shift[g][h] = idx(Rg^T * Rh)
        int g = tid / 24, h = tid % 24;
        int R[9];
        for (int a = 0; a < 3; a++)
            for (int b = 0; b < 3; b++) {
                int v = 0;
                for (int c = 0; c < 3; c++) v += mats[g][c*3+a] * mats[h][c*3+b];
                R[a*3+b] = v;
            }
        int idx = 0;
        for (int j = 0; j < 24; j++) {
            bool eq = true;
            for (int q = 0; q < 9; q++) if (mats[j][q] != R[q]) { eq = false; break; }
            if (eq) { idx = j; break; }
        }
        g_shift[g][h] = idx;
    }
    if (tid < 648) {                       // rot_idx[g][j]
        int g = tid / 27, j = tid % 27;
        int x0 = j / 9 - 1, x1 = (j / 3) % 3 - 1, x2 = j % 3 - 1;
        int r0 = x0*mats[g][0] + x1*mats[g][3] + x2*mats[g][6] + 1;
        int r1 = x0*mats[g][1] + x1*mats[g][4] + x2*mats[g][7] + 1;
        int r2 = x0*mats[g][2] + x1*mats[g][5] + x2*mats[g][8] + 1;
        g_rot[g][j] = r0*9 + r1*3 + r2;
    }
}

__global__ void build_wt_kernel(const float* __restrict__ gw) {
    int idx = blockIdx.x * blockDim.x + threadIdx.x;
    if (idx >= NCH * NCH) return;
    int n = idx / NCH, k = idx % NCH;
    int o = n / GG, z = n % GG;
    int i = k / GG, g = k % GG;
    g_Wt[idx] = tf32r(gw[(g_shift[z][g] * OO + o) * II + i]);
}

__global__ void build_tfb_kernel(const float* __restrict__ tw) {
    int idx = blockIdx.x * blockDim.x + threadIdx.x;
    if (idx >= NCH * 27) return;
    int n = idx / 27, j = idx % 27;
    g_TFB[idx] = tw[(n / GG) * 27 + g_rot[n % GG][j]];
}

// ================= tf32 mma.sync GEMM, cp.async 4-stage (k8) =================
// C[n][m] = sum_k Wt[n][k] * x[k][m]; CTA 128n x 128m, 48 k-steps of 8.
// 256 threads = 8 warps (2 n-halves x 4 m-quarters); warp tile 64n x 32m.
// A smem [128][12] per stage (conflict-free frags), B smem [8][136] per stage.
__global__ void __launch_bounds__(256, 2)
gemm_mma_kernel(const float* __restrict__ x, const float* __restrict__ gbias) {
    __shared__ float As[4][128][12];
    __shared__ float Bs[4][8][136];

    const int tid  = threadIdx.x;
    const int lane = tid & 31;
    const int wid  = tid >> 5;
    const int wr   = wid >> 2;            // 0..1 : n 64-half
    const int wc   = wid & 3;             // 0..3 : m 32-quarter
    const int n0   = blockIdx.x * 128;    // 0,128,256
    const int m0   = blockIdx.y * 128;
    const int b    = m0 >> 15;
    const int ms   = m0 & (SS - 1);

    const int gid  = lane >> 2;           // 0..7
    const int tig  = lane & 3;            // 0..3

    float acc[4][4][4];
    #pragma unroll
    for (int i = 0; i < 4; i++)
        #pragma unroll
        for (int j = 0; j < 4; j++)
            #pragma unroll
            for (int q = 0; q < 4; q++) acc[i][j][q] = 0.0f;

    // per-thread cp.async slots (1 A float4 + 1 B float4 per stage)
    const int arow = tid >> 1, ac4 = (tid & 1) << 2;
    const int brow = tid >> 5, bc4 = (tid & 31) << 2;
    const float* asrc_base = &g_Wt[(n0 + arow) * NCH + ac4];
    const float* bsrc_base = &x[(((size_t)(b * NCH + brow)) << 15) + ms + bc4];

    auto prefetch = [&](int ks, int s) {
        const int k0 = ks * 8;
        cpasync16(smem_u32(&As[s][arow][ac4]), asrc_base + k0);
        cpasync16(smem_u32(&Bs[s][brow][bc4]), bsrc_base + ((size_t)k0 << 15));
    };

    prefetch(0, 0); CP_COMMIT();
    prefetch(1, 1); CP_COMMIT();
    prefetch(2, 2); CP_COMMIT();

    for (int s = 0; s < 48; s++) {
        const int cur = s & 3;
        CP_WAIT(2);
        __syncthreads();
        if (s < 45) prefetch(s + 3, (s + 3) & 3);
        CP_COMMIT();

        uint32_t af[4][4];
        #pragma unroll
        for (int mi = 0; mi < 4; mi++) {
            int row = wr * 64 + mi * 16 + gid;
            af[mi][0] = __float_as_uint(As[cur][row][tig]);
            af[mi][1] = __float_as_uint(As[cur][row + 8][tig]);
            af[mi][2] = __float_as_uint(As[cur][row][tig + 4]);
            af[mi][3] = __float_as_uint(As[cur][row + 8][tig + 4]);
        }
        uint32_t bf[4][2];
        #pragma unroll
        for (int ni = 0; ni < 4; ni++) {
            int m = wc * 32 + ni * 8 + gid;
            bf[ni][0] = __float_as_uint(tf32r(Bs[cur][tig][m]));
            bf[ni][1] = __float_as_uint(tf32r(Bs[cur][tig + 4][m]));
        }
        #pragma unroll
        for (int mi = 0; mi < 4; mi++)
            #pragma unroll
            for (int ni = 0; ni < 4; ni++)
                mma_tf32(acc[mi][ni], af[mi], bf[ni][0], bf[ni][1]);
    }

    // epilogue: add bias, direct float2 stores
    #pragma unroll
    for (int mi = 0; mi < 4; mi++) {
        int nlo = n0 + wr * 64 + mi * 16 + gid;
        float blo = gbias[nlo / GG];
        float bhi = gbias[(nlo + 8) / GG];
        float* rowlo = &g_y[(((size_t)(b * NCH + nlo)) << 15) + ms];
        float* rowhi = rowlo + ((size_t)8 << 15);
        #pragma unroll
        for (int ni = 0; ni < 4; ni++) {
            int m = wc * 32 + ni * 8 + tig * 2;
            float2 lo = make_float2(acc[mi][ni][0] + blo, acc[mi][ni][1] + blo);
            float2 hi = make_float2(acc[mi][ni][2] + bhi, acc[mi][ni][3] + bhi);
            *(float2*)(rowlo + m) = lo;
            *(float2*)(rowhi + m) = hi;
        }
    }
}

// ================= depthwise 3x3x3 conv + bias + leaky ReLU (f32x2) =========
// Halo fill: vector zero pass + coalesced float4 interior loads.
__global__ void __launch_bounds__(256)
conv_kernel(float* __restrict__ out, const float* __restrict__ tbias) {
    __shared__ float tile[10][34][34];     // 46240 B
    __shared__ float2 tap2[27];
    __shared__ float sbias;

    const int ch = blockIdx.x >> 2;
    const int h0 = (blockIdx.x & 3) * 8;
    const int tid = threadIdx.x;

    const float* ybase = g_y + (size_t)ch * SS;
    if (tid < 27) {
        float t = g_TFB[(ch % NCH) * 27 + tid];
        tap2[tid] = make_float2(t, t);
    }
    if (tid == 27) sbias = tbias[0];

    // zero pass (vectorized; 10*34*34 = 11560 = 2890 float4)
    {
        float4* tz = (float4*)&tile[0][0][0];
        for (int i = tid; i < 2890; i += 256) tz[i] = make_float4(0.f, 0.f, 0.f, 0.f);
    }
    __syncthreads();

    // interior: coalesced float4 GMEM reads, scalar STS
    {
        const int ww = tid >> 3;           // 0..31
        const int dd0 = (tid & 7) << 2;    // 0,4,...,28
        #pragma unroll
        for (int hh = 0; hh < 10; hh++) {
            int gh = h0 + hh - 1;
            if (gh >= 0 && gh < 32) {
                float4 v = *(const float4*)&ybase[(gh * 32 + ww) * 32 + dd0];
                float* trow = &tile[hh][ww + 1][1 + dd0];
                trow[0] = v.x; trow[1] = v.y; trow[2] = v.z; trow[3] = v.w;
            }
        }
    }
    __syncthreads();

    float* obase = out + (size_t)ch * SS + (size_t)h0 * 1024;
    #pragma unroll 1
    for (int it = 0; it < 4; it++) {
        int q = tid + it * 256;            // 0..1023
        int d0 = (q & 3) << 3;             // 0,8,16,24
        int w = (q >> 2) & 31;
        int h = q >> 7;
        ull a0 = dup2(sbias), a1 = a0, a2 = a0, a3 = a0;
        #pragma unroll
        for (int a = 0; a < 3; a++)
            #pragma unroll
            for (int bq = 0; bq < 3; bq++) {
                const float* rp = &tile[h + a][w + bq][d0];
                float2 f0 = *(const float2*)(rp + 0);
                float2 f1 = *(const float2*)(rp + 2);
                float2 f2 = *(const float2*)(rp + 4);
                float2 f3 = *(const float2*)(rp + 6);
                float2 f4 = *(const float2*)(rp + 8);
                ull w0 = pk2(f0.x, f0.y), w1 = pk2(f1.x, f1.y), w2 = pk2(f2.x, f2.y);
                ull w3 = pk2(f3.x, f3.y), w4 = pk2(f4.x, f4.y);
                ull s0 = pk2(f0.y, f1.x), s1 = pk2(f1.y, f2.x);
                ull s2 = pk2(f2.y, f3.x), s3 = pk2(f3.y, f4.x);
                const ull* tp = (const ull*)&tap2[a * 9 + bq * 3];
                ull t0 = tp[0], t1 = tp[1], t2 = tp[2];
                a0 = ffma2(t0, w0, a0); a0 = ffma2(t1, s0, a0); a0 = ffma2(t2, w1, a0);
                a1 = ffma2(t0, w1, a1); a1 = ffma2(t1, s1, a1); a1 = ffma2(t2, w2, a1);
                a2 = ffma2(t0, w2, a2); a2 = ffma2(t1, s2, a2); a2 = ffma2(t2, w3, a2);
                a3 = ffma2(t0, w3, a3); a3 = ffma2(t1, s3, a3); a3 = ffma2(t2, w4, a3);
            }
        float2 u0 = unpack2(a0), u1 = unpack2(a1), u2 = unpack2(a2), u3 = unpack2(a3);
        float4 o0, o1;
        o0.x = u0.x > 0.0f ? u0.x : 0.01f * u0.x;
        o0.y = u0.y > 0.0f ? u0.y : 0.01f * u0.y;
        o0.z = u1.x > 0.0f ? u1.x : 0.01f * u1.x;
        o0.w = u1.y > 0.0f ? u1.y : 0.01f * u1.y;
        o1.x = u2.x > 0.0f ? u2.x : 0.01f * u2.x;
        o1.y = u2.y > 0.0f ? u2.y : 0.01f * u2.y;
        o1.z = u3.x > 0.0f ? u3.x : 0.01f * u3.x;
        o1.w = u3.y > 0.0f ? u3.y : 0.01f * u3.y;
        float* dst = obase + ((h * 32 + w) * 32 + d0);
        *(float4*)dst = o0;
        *(float4*)(dst + 4) = o1;
    }
}

// ---------------- launch ----------------
extern "C" void kernel_launch(void* const* d_in, const int* in_sizes, int n_in,
                              void* d_out, int out_size) {
    const float* x  = (const float*)d_in[0];
    const float* gw = (const float*)d_in[1];
    const float* tw = (const float*)d_in[2];
    const float* gb = (const float*)d_in[3];
    const float* tb = (const float*)d_in[4];
    float* out = (float*)d_out;

    build_tables_kernel<<<1, 648>>>();
    build_wt_kernel<<<(NCH * NCH + 255) / 256, 256>>>(gw);
    build_tfb_kernel<<<(NCH * 27 + 255) / 256, 256>>>(tw);

    dim3 gg(3, 512);      // x = n-tile fastest: CTAs sharing an m-stripe co-scheduled
    gemm_mma_kernel<<<gg, 256>>>(x, gb);
    conv_kernel<<<3072, 256>>>(out, tb);
}

// round 7
// speedup vs baseline: 5.0932x; 1.2848x over previous
#include <cuda_runtime.h>
#include <cuda_fp16.h>
#include <cstdint>

using ull = unsigned long long;

#define GG 24
#define II 16
#define OO 16
#define SS 32768            // 32*32*32 spatial
#define NCH 384             // I*G == O*G
#define K2  192             // NCH/2 (fp16 k-pairs)
#define BB 2

// ---------------- device scratch (no allocations allowed) ----------------
__device__ int      g_shift[GG][GG];
__device__ int      g_rot[GG][27];
__device__ uint32_t g_Wh[NCH * K2];        // W^T[n][k-pair] packed f16x2
__device__ uint32_t g_xh[BB * K2 * SS];    // x[b][k-pair][m] packed f16x2 (50 MB)
__device__ float    g_TFB[NCH * 27];       // rotated depthwise taps per (o,z)
__device__ float    g_y[BB * NCH * SS];    // intermediate y (100 MB)

__device__ __forceinline__ uint32_t smem_u32(const void* p) {
    uint32_t a;
    asm("{ .reg .u64 t; cvta.to.shared.u64 t, %1; cvt.u32.u64 %0, t; }" : "=r"(a) : "l"(p));
    return a;
}
__device__ __forceinline__ void mma_f16(float* c, const uint32_t* a, uint32_t b0, uint32_t b1) {
    asm volatile(
        "mma.sync.aligned.m16n8k16.row.col.f32.f16.f16.f32 "
        "{%0,%1,%2,%3}, {%4,%5,%6,%7}, {%8,%9}, {%0,%1,%2,%3};"
        : "+f"(c[0]), "+f"(c[1]), "+f"(c[2]), "+f"(c[3])
        : "r"(a[0]), "r"(a[1]), "r"(a[2]), "r"(a[3]), "r"(b0), "r"(b1));
}
__device__ __forceinline__ void cpasync16(uint32_t dst, const void* src) {
    asm volatile("cp.async.cg.shared.global [%0], [%1], 16;" :: "r"(dst), "l"(src));
}
#define CP_COMMIT() asm volatile("cp.async.commit_group;" ::: "memory")
#define CP_WAIT(n)  asm volatile("cp.async.wait_group %0;" :: "n"(n) : "memory")

__device__ __forceinline__ uint32_t packh2(float lo, float hi) {
    __half2 h = __halves2half2(__float2half(lo), __float2half(hi));
    return *reinterpret_cast<uint32_t*>(&h);
}

// ---- packed f32x2 helpers (conv) ----
__device__ __forceinline__ ull ffma2(ull a, ull b, ull c) {
    ull d;
    asm("fma.rn.f32x2 %0, %1, %2, %3;" : "=l"(d) : "l"(a), "l"(b), "l"(c));
    return d;
}
__device__ __forceinline__ ull dup2(float f) {
    ull d;
    asm("mov.b64 %0, {%1, %1};" : "=l"(d) : "f"(f));
    return d;
}
__device__ __forceinline__ ull pk2(float lo, float hi) {
    ull d;
    asm("mov.b64 %0, {%1, %2};" : "=l"(d) : "f"(lo), "f"(hi));
    return d;
}
__device__ __forceinline__ float2 unpack2(ull u) {
    float2 r;
    asm("mov.b64 {%0, %1}, %2;" : "=f"(r.x), "=f"(r.y) : "l"(u));
    return r;
}

// ---------------- table construction (replicates numpy enumeration) -----
__global__ void build_tables_kernel() {
    __shared__ int mats[24][9];
    int tid = threadIdx.x;
    if (tid == 0) {
        const int perms[6][3] = {{0,1,2},{0,2,1},{1,0,2},{1,2,0},{2,0,1},{2,1,0}};
        int cnt = 0;
        for (int p = 0; p < 6; p++)
            for (int sb = 0; sb < 8; sb++) {
                int s0 = (sb & 4) ? -1 : 1, s1 = (sb & 2) ? -1 : 1, s2 = (sb & 1) ? -1 : 1;
                int M[9] = {0,0,0,0,0,0,0,0,0};
                M[0*3 + perms[p][0]] = s0;
                M[1*3 + perms[p][1]] = s1;
                M[2*3 + perms[p][2]] = s2;
                int det = M[0]*(M[4]*M[8]-M[5]*M[7]) - M[1]*(M[3]*M[8]-M[5]*M[6]) + M[2]*(M[3]*M[7]-M[4]*M[6]);
                if (det == 1) { for (int q = 0; q < 9; q++) mats[cnt][q] = M[q]; cnt++; }
            }
    }
    __syncthreads();
    if (tid < 576) {                       // shift[g][h] = idx(Rg^T * Rh)
        int g = tid / 24, h = tid % 24;
        int R[9];
        for (int a = 0; a < 3; a++)
            for (int b = 0; b < 3; b++) {
                int v = 0;
                for (int c = 0; c < 3; c++) v += mats[g][c*3+a] * mats[h][c*3+b];
                R[a*3+b] = v;
            }
        int idx = 0;
        for (int j = 0; j < 24; j++) {
            bool eq = true;
            for (int q = 0; q < 9; q++) if (mats[j][q] != R[q]) { eq = false; break; }
            if (eq) { idx = j; break; }
        }
        g_shift[g][h] = idx;
    }
    if (tid < 648) {                       // rot_idx[g][j]
        int g = tid / 27, j = tid % 27;
        int x0 = j / 9 - 1, x1 = (j / 3) % 3 - 1, x2 = j % 3 - 1;
        int r0 = x0*mats[g][0] + x1*mats[g][3] + x2*mats[g][6] + 1;
        int r1 = x0*mats[g][1] + x1*mats[g][4] + x2*mats[g][7] + 1;
        int r2 = x0*mats[g][2] + x1*mats[g][5] + x2*mats[g][8] + 1;
        g_rot[g][j] = r0*9 + r1*3 + r2;
    }
}

// W^T[n][k2] = pack(W[2k2][n], W[2k2+1][n]) in fp16
__global__ void build_wh_kernel(const float* __restrict__ gw) {
    int idx = blockIdx.x * blockDim.x + threadIdx.x;
    if (idx >= NCH * K2) return;
    int n = idx / K2, k2 = idx % K2;
    int o = n / GG, z = n % GG;
    int k0 = 2 * k2, k1 = 2 * k2 + 1;
    int i0 = k0 / GG, gg0 = k0 % GG;
    int i1 = k1 / GG, gg1 = k1 % GG;
    float w0 = gw[(g_shift[z][gg0] * OO + o) * II + i0];
    float w1 = gw[(g_shift[z][gg1] * OO + o) * II + i1];
    g_Wh[idx] = packh2(w0, w1);
}

__global__ void build_tfb_kernel(const float* __restrict__ tw) {
    int idx = blockIdx.x * blockDim.x + threadIdx.x;
    if (idx >= NCH * 27) return;
    int n = idx / 27, j = idx % 27;
    g_TFB[idx] = tw[(n / GG) * 27 + g_rot[n % GG][j]];
}

// x -> fp16 k-pair packed: g_xh[(b*K2 + k2)*SS + m] = pack(x[b][2k2][m], x[b][2k2+1][m])
__global__ void __launch_bounds__(256)
convert_x_kernel(const float* __restrict__ x) {
    int idx = blockIdx.x * blockDim.x + threadIdx.x;   // 0 .. BB*K2*8192-1
    int m4 = (idx & 8191) << 2;
    int k2 = (idx >> 13) % K2;
    int b  = idx / (K2 * 8192);
    const float* r0 = &x[(((size_t)(b * NCH + 2 * k2)) << 15) + m4];
    float4 a = *(const float4*)r0;
    float4 c = *(const float4*)(r0 + SS);
    uint4 o;
    o.x = packh2(a.x, c.x);
    o.y = packh2(a.y, c.y);
    o.z = packh2(a.z, c.z);
    o.w = packh2(a.w, c.w);
    *(uint4*)&g_xh[(((size_t)(b * K2 + k2)) << 15) + m4] = o;
}

// ================= fp16 mma.sync GEMM, cp.async 4-stage (k16) =================
// C[n][m] = sum_k Wt[n][k] * x[k][m]; CTA 128n x 128m, 24 k-steps of 16.
// 256 threads = 8 warps (2 n-halves x 4 m-quarters); warp tile 64n x 32m.
// A smem [128][12] u32/stage (8 used, pitch-12 conflict-free), B smem [8][136] u32.
__global__ void __launch_bounds__(256, 2)
gemm_mma_kernel(const float* __restrict__ gbias) {
    __shared__ uint32_t As[4][128][12];
    __shared__ uint32_t Bs[4][8][136];

    const int tid  = threadIdx.x;
    const int lane = tid & 31;
    const int wid  = tid >> 5;
    const int wr   = wid >> 2;            // 0..1 : n 64-half
    const int wc   = wid & 3;             // 0..3 : m 32-quarter
    const int n0   = blockIdx.x * 128;    // 0,128,256
    const int m0   = blockIdx.y * 128;
    const int b    = m0 >> 15;
    const int ms   = m0 & (SS - 1);

    const int gid  = lane >> 2;           // 0..7
    const int tig  = lane & 3;            // 0..3

    float acc[4][4][4];
    #pragma unroll
    for (int i = 0; i < 4; i++)
        #pragma unroll
        for (int j = 0; j < 4; j++)
            #pragma unroll
            for (int q = 0; q < 4; q++) acc[i][j][q] = 0.0f;

    // per-thread cp.async slots (1 A 16B + 1 B 16B per stage)
    const int arow = tid >> 1, ac = (tid & 1) << 2;      // A: [128 n][8 k2]
    const int brow = tid >> 5, bc = (tid & 31) << 2;     // B: [8 k2][128 m]
    const uint32_t* asrc_base = &g_Wh[(n0 + arow) * K2 + ac];
    const uint32_t* bsrc_base = &g_xh[(((size_t)(b * K2 + brow)) << 15) + ms + bc];

    auto prefetch = [&](int ks, int s) {
        const int k20 = ks * 8;
        cpasync16(smem_u32(&As[s][arow][ac]), asrc_base + k20);
        cpasync16(smem_u32(&Bs[s][brow][bc]), bsrc_base + ((size_t)k20 << 15));
    };

    prefetch(0, 0); CP_COMMIT();
    prefetch(1, 1); CP_COMMIT();
    prefetch(2, 2); CP_COMMIT();

    for (int s = 0; s < 24; s++) {
        const int cur = s & 3;
        CP_WAIT(2);
        __syncthreads();
        if (s < 21) prefetch(s + 3, (s + 3) & 3);
        CP_COMMIT();

        uint32_t af[4][4];
        #pragma unroll
        for (int mi = 0; mi < 4; mi++) {
            int row = wr * 64 + mi * 16 + gid;
            af[mi][0] = As[cur][row][tig];
            af[mi][1] = As[cur][row + 8][tig];
            af[mi][2] = As[cur][row][tig + 4];
            af[mi][3] = As[cur][row + 8][tig + 4];
        }
        uint32_t bf[4][2];
        #pragma unroll
        for (int ni = 0; ni < 4; ni++) {
            int m = wc * 32 + ni * 8 + gid;
            bf[ni][0] = Bs[cur][tig][m];
            bf[ni][1] = Bs[cur][tig + 4][m];
        }
        #pragma unroll
        for (int mi = 0; mi < 4; mi++)
            #pragma unroll
            for (int ni = 0; ni < 4; ni++)
                mma_f16(acc[mi][ni], af[mi], bf[ni][0], bf[ni][1]);
        __syncthreads();
    }

    // epilogue: add bias, direct float2 stores
    #pragma unroll
    for (int mi = 0; mi < 4; mi++) {
        int nlo = n0 + wr * 64 + mi * 16 + gid;
        float blo = gbias[nlo / GG];
        float bhi = gbias[(nlo + 8) / GG];
        float* rowlo = &g_y[(((size_t)(b * NCH + nlo)) << 15) + ms];
        float* rowhi = rowlo + ((size_t)8 << 15);
        #pragma unroll
        for (int ni = 0; ni < 4; ni++) {
            int m = wc * 32 + ni * 8 + tig * 2;
            float2 lo = make_float2(acc[mi][ni][0] + blo, acc[mi][ni][1] + blo);
            float2 hi = make_float2(acc[mi][ni][2] + bhi, acc[mi][ni][3] + bhi);
            *(float2*)(rowlo + m) = lo;
            *(float2*)(rowhi + m) = hi;
        }
    }
}

// ================= depthwise 3x3x3 conv + bias + leaky ReLU (f32x2) =========
__global__ void __launch_bounds__(256)
conv_kernel(float* __restrict__ out, const float* __restrict__ tbias) {
    __shared__ float tile[10][34][34];
    __shared__ float2 tap2[27];
    __shared__ float sbias;

    const int ch = blockIdx.x >> 2;
    const int h0 = (blockIdx.x & 3) * 8;
    const int tid = threadIdx.x;

    const float* ybase = g_y + (size_t)ch * SS;
    if (tid < 27) {
        float t = g_TFB[(ch % NCH) * 27 + tid];
        tap2[tid] = make_float2(t, t);
    }
    if (tid == 27) sbias = tbias[0];

    {
        float4* tz = (float4*)&tile[0][0][0];
        for (int i = tid; i < 2890; i += 256) tz[i] = make_float4(0.f, 0.f, 0.f, 0.f);
    }
    __syncthreads();

    {
        const int ww = tid >> 3;
        const int dd0 = (tid & 7) << 2;
        #pragma unroll
        for (int hh = 0; hh < 10; hh++) {
            int gh = h0 + hh - 1;
            if (gh >= 0 && gh < 32) {
                float4 v = *(const float4*)&ybase[(gh * 32 + ww) * 32 + dd0];
                float* trow = &tile[hh][ww + 1][1 + dd0];
                trow[0] = v.x; trow[1] = v.y; trow[2] = v.z; trow[3] = v.w;
            }
        }
    }
    __syncthreads();

    float* obase = out + (size_t)ch * SS + (size_t)h0 * 1024;
    #pragma unroll 1
    for (int it = 0; it < 4; it++) {
        int q = tid + it * 256;
        int d0 = (q & 3) << 3;
        int w = (q >> 2) & 31;
        int h = q >> 7;
        ull a0 = dup2(sbias), a1 = a0, a2 = a0, a3 = a0;
        #pragma unroll
        for (int a = 0; a < 3; a++)
            #pragma unroll
            for (int bq = 0; bq < 3; bq++) {
                const float* rp = &tile[h + a][w + bq][d0];
                float2 f0 = *(const float2*)(rp + 0);
                float2 f1 = *(const float2*)(rp + 2);
                float2 f2 = *(const float2*)(rp + 4);
                float2 f3 = *(const float2*)(rp + 6);
                float2 f4 = *(const float2*)(rp + 8);
                ull w0 = pk2(f0.x, f0.y), w1 = pk2(f1.x, f1.y), w2 = pk2(f2.x, f2.y);
                ull w3 = pk2(f3.x, f3.y), w4 = pk2(f4.x, f4.y);
                ull s0 = pk2(f0.y, f1.x), s1 = pk2(f1.y, f2.x);
                ull s2 = pk2(f2.y, f3.x), s3 = pk2(f3.y, f4.x);
                const ull* tp = (const ull*)&tap2[a * 9 + bq * 3];
                ull t0 = tp[0], t1 = tp[1], t2 = tp[2];
                a0 = ffma2(t0, w0, a0); a0 = ffma2(t1, s0, a0); a0 = ffma2(t2, w1, a0);
                a1 = ffma2(t0, w1, a1); a1 = ffma2(t1, s1, a1); a1 = ffma2(t2, w2, a1);
                a2 = ffma2(t0, w2, a2); a2 = ffma2(t1, s2, a2); a2 = ffma2(t2, w3, a2);
                a3 = ffma2(t0, w3, a3); a3 = ffma2(t1, s3, a3); a3 = ffma2(t2, w4, a3);
            }
        float2 u0 = unpack2(a0), u1 = unpack2(a1), u2 = unpack2(a2), u3 = unpack2(a3);
        float4 o0, o1;
        o0.x = u0.x > 0.0f ? u0.x : 0.01f * u0.x;
        o0.y = u0.y > 0.0f ? u0.y : 0.01f * u0.y;
        o0.z = u1.x > 0.0f ? u1.x : 0.01f * u1.x;
        o0.w = u1.y > 0.0f ? u1.y : 0.01f * u1.y;
        o1.x = u2.x > 0.0f ? u2.x : 0.01f * u2.x;
        o1.y = u2.y > 0.0f ? u2.y : 0.01f * u2.y;
        o1.z = u3.x > 0.0f ? u3.x : 0.01f * u3.x;
        o1.w = u3.y > 0.0f ? u3.y : 0.01f * u3.y;
        float* dst = obase + ((h * 32 + w) * 32 + d0);
        *(float4*)dst = o0;
        *(float4*)(dst + 4) = o1;
    }
}

// ---------------- launch ----------------
extern "C" void kernel_launch(void* const* d_in, const int* in_sizes, int n_in,
                              void* d_out, int out_size) {
    const float* x  = (const float*)d_in[0];
    const float* gw = (const float*)d_in[1];
    const float* tw = (const float*)d_in[2];
    const float* gb = (const float*)d_in[3];
    const float* tb = (const float*)d_in[4];
    float* out = (float*)d_out;

    build_tables_kernel<<<1, 648>>>();
    build_wh_kernel<<<(NCH * K2 + 255) / 256, 256>>>(gw);
    build_tfb_kernel<<<(NCH * 27 + 255) / 256, 256>>>(tw);
    convert_x_kernel<<<BB * K2 * 8192 / 256, 256>>>(x);

    dim3 gg(3, 512);      // x = n-tile fastest: CTAs sharing an m-stripe co-scheduled
    gemm_mma_kernel<<<gg, 256>>>(gb);
    conv_kernel<<<3072, 256>>>(out, tb);
}

// round 8
// speedup vs baseline: 5.3271x; 1.0459x over previous
#include <cuda_runtime.h>
#include <cuda_fp16.h>
#include <cstdint>

using ull = unsigned long long;

#define GG 24
#define II 16
#define OO 16
#define SS 32768            // 32*32*32 spatial
#define NCH 384             // I*G == O*G
#define K2  192             // NCH/2 (fp16 k-pairs)
#define BB 2

// ---------------- device scratch (no allocations allowed) ----------------
__device__ int      g_shift[GG][GG];
__device__ int      g_rot[GG][27];
__device__ uint32_t g_Wh[NCH * K2];        // W^T[n][k-pair] packed f16x2
__device__ uint32_t g_xh[BB * K2 * SS];    // x[b][k-pair][m] packed f16x2 (50 MB)
__device__ float    g_TFB[NCH * 27];       // rotated depthwise taps per (o,z)
__device__ float    g_y[BB * NCH * SS];    // intermediate y (100 MB)

__device__ __forceinline__ uint32_t smem_u32(const void* p) {
    uint32_t a;
    asm("{ .reg .u64 t; cvta.to.shared.u64 t, %1; cvt.u32.u64 %0, t; }" : "=r"(a) : "l"(p));
    return a;
}
__device__ __forceinline__ void mma_f16(float* c, const uint32_t* a, uint32_t b0, uint32_t b1) {
    asm volatile(
        "mma.sync.aligned.m16n8k16.row.col.f32.f16.f16.f32 "
        "{%0,%1,%2,%3}, {%4,%5,%6,%7}, {%8,%9}, {%0,%1,%2,%3};"
        : "+f"(c[0]), "+f"(c[1]), "+f"(c[2]), "+f"(c[3])
        : "r"(a[0]), "r"(a[1]), "r"(a[2]), "r"(a[3]), "r"(b0), "r"(b1));
}
__device__ __forceinline__ void cpasync16(uint32_t dst, const void* src) {
    asm volatile("cp.async.cg.shared.global [%0], [%1], 16;" :: "r"(dst), "l"(src));
}
#define CP_COMMIT() asm volatile("cp.async.commit_group;" ::: "memory")
#define CP_WAIT(n)  asm volatile("cp.async.wait_group %0;" :: "n"(n) : "memory")

__device__ __forceinline__ uint32_t packh2(float lo, float hi) {
    __half2 h = __halves2half2(__float2half(lo), __float2half(hi));
    return *reinterpret_cast<uint32_t*>(&h);
}

// ---- packed f32x2 helpers (conv) ----
__device__ __forceinline__ ull ffma2(ull a, ull b, ull c) {
    ull d;
    asm("fma.rn.f32x2 %0, %1, %2, %3;" : "=l"(d) : "l"(a), "l"(b), "l"(c));
    return d;
}
__device__ __forceinline__ ull dup2(float f) {
    ull d;
    asm("mov.b64 %0, {%1, %1};" : "=l"(d) : "f"(f));
    return d;
}
__device__ __forceinline__ ull pk2(float lo, float hi) {
    ull d;
    asm("mov.b64 %0, {%1, %2};" : "=l"(d) : "f"(lo), "f"(hi));
    return d;
}
__device__ __forceinline__ float2 unpack2(ull u) {
    float2 r;
    asm("mov.b64 {%0, %1}, %2;" : "=f"(r.x), "=f"(r.y) : "l"(u));
    return r;
}

// ---------------- table construction (replicates numpy enumeration) -----
__global__ void build_tables_kernel() {
    __shared__ int mats[24][9];
    int tid = threadIdx.x;
    if (tid == 0) {
        const int perms[6][3] = {{0,1,2},{0,2,1},{1,0,2},{1,2,0},{2,0,1},{2,1,0}};
        int cnt = 0;
        for (int p = 0; p < 6; p++)
            for (int sb = 0; sb < 8; sb++) {
                int s0 = (sb & 4) ? -1 : 1, s1 = (sb & 2) ? -1 : 1, s2 = (sb & 1) ? -1 : 1;
                int M[9] = {0,0,0,0,0,0,0,0,0};
                M[0*3 + perms[p][0]] = s0;
                M[1*3 + perms[p][1]] = s1;
                M[2*3 + perms[p][2]] = s2;
                int det = M[0]*(M[4]*M[8]-M[5]*M[7]) - M[1]*(M[3]*M[8]-M[5]*M[6]) + M[2]*(M[3]*M[7]-M[4]*M[6]);
                if (det == 1) { for (int q = 0; q < 9; q++) mats[cnt][q] = M[q]; cnt++; }
            }
    }
    __syncthreads();
    if (tid < 576) {                       // shift[g][h] = idx(Rg^T * Rh)
        int g = tid / 24, h = tid % 24;
        int R[9];
        for (int a = 0; a < 3; a++)
            for (int b = 0; b < 3; b++) {
                int v = 0;
                for (int c = 0; c < 3; c++) v += mats[g][c*3+a] * mats[h][c*3+b];
                R[a*3+b] = v;
            }
        int idx = 0;
        for (int j = 0; j < 24; j++) {
            bool eq = true;
            for (int q = 0; q < 9; q++) if (mats[j][q] != R[q]) { eq = false; break; }
            if (eq) { idx = j; break; }
        }
        g_shift[g][h] = idx;
    }
    if (tid < 648) {                       // rot_idx[g][j]
        int g = tid / 27, j = tid % 27;
        int x0 = j / 9 - 1, x1 = (j / 3) % 3 - 1, x2 = j % 3 - 1;
        int r0 = x0*mats[g][0] + x1*mats[g][3] + x2*mats[g][6] + 1;
        int r1 = x0*mats[g][1] + x1*mats[g][4] + x2*mats[g][7] + 1;
        int r2 = x0*mats[g][2] + x1*mats[g][5] + x2*mats[g][8] + 1;
        g_rot[g][j] = r0*9 + r1*3 + r2;
    }
}

// W^T[n][k2] = pack(W[2k2][n], W[2k2+1][n]) in fp16
__global__ void build_wh_kernel(const float* __restrict__ gw) {
    int idx = blockIdx.x * blockDim.x + threadIdx.x;
    if (idx >= NCH * K2) return;
    int n = idx / K2, k2 = idx % K2;
    int o = n / GG, z = n % GG;
    int k0 = 2 * k2, k1 = 2 * k2 + 1;
    int i0 = k0 / GG, gg0 = k0 % GG;
    int i1 = k1 / GG, gg1 = k1 % GG;
    float w0 = gw[(g_shift[z][gg0] * OO + o) * II + i0];
    float w1 = gw[(g_shift[z][gg1] * OO + o) * II + i1];
    g_Wh[idx] = packh2(w0, w1);
}

__global__ void build_tfb_kernel(const float* __restrict__ tw) {
    int idx = blockIdx.x * blockDim.x + threadIdx.x;
    if (idx >= NCH * 27) return;
    int n = idx / 27, j = idx % 27;
    g_TFB[idx] = tw[(n / GG) * 27 + g_rot[n % GG][j]];
}

// x -> fp16 k-pair packed
__global__ void __launch_bounds__(256)
convert_x_kernel(const float* __restrict__ x) {
    int idx = blockIdx.x * blockDim.x + threadIdx.x;
    int m4 = (idx & 8191) << 2;
    int k2 = (idx >> 13) % K2;
    int b  = idx / (K2 * 8192);
    const float* r0 = &x[(((size_t)(b * NCH + 2 * k2)) << 15) + m4];
    float4 a = *(const float4*)r0;
    float4 c = *(const float4*)(r0 + SS);
    uint4 o;
    o.x = packh2(a.x, c.x);
    o.y = packh2(a.y, c.y);
    o.z = packh2(a.z, c.z);
    o.w = packh2(a.w, c.w);
    *(uint4*)&g_xh[(((size_t)(b * K2 + k2)) << 15) + m4] = o;
}

// ================= fp16 mma.sync GEMM, cp.async 4-stage (k16) =================
// CTA 128n x 128m, 24 k-steps of 16; 8 warps (2 n-halves x 4 m-quarters).
// A frags via ldmatrix.x4 (pitch-12 conflict-free); one __syncthreads per step.
__global__ void __launch_bounds__(256, 2)
gemm_mma_kernel(const float* __restrict__ gbias) {
    __shared__ uint32_t As[4][128][12];
    __shared__ uint32_t Bs[4][8][136];

    const int tid  = threadIdx.x;
    const int lane = tid & 31;
    const int wid  = tid >> 5;
    const int wr   = wid >> 2;            // 0..1 : n 64-half
    const int wc   = wid & 3;             // 0..3 : m 32-quarter
    const int n0   = blockIdx.x * 128;    // 0,128,256
    const int m0   = blockIdx.y * 128;
    const int b    = m0 >> 15;
    const int ms   = m0 & (SS - 1);

    const int gid  = lane >> 2;           // 0..7
    const int tig  = lane & 3;            // 0..3

    float acc[4][4][4];
    #pragma unroll
    for (int i = 0; i < 4; i++)
        #pragma unroll
        for (int j = 0; j < 4; j++)
            #pragma unroll
            for (int q = 0; q < 4; q++) acc[i][j][q] = 0.0f;

    // cp.async slots
    const int arow = tid >> 1, ac = (tid & 1) << 2;      // A: [128 n][8 k2]
    const int brow = tid >> 5, bc = (tid & 31) << 2;     // B: [8 k2][128 m]
    const uint32_t* asrc_base = &g_Wh[(n0 + arow) * K2 + ac];
    const uint32_t* bsrc_base = &g_xh[(((size_t)(b * K2 + brow)) << 15) + ms + bc];

    auto prefetch = [&](int ks, int s) {
        const int k20 = ks * 8;
        cpasync16(smem_u32(&As[s][arow][ac]), asrc_base + k20);
        cpasync16(smem_u32(&Bs[s][brow][bc]), bsrc_base + ((size_t)k20 << 15));
    };

    // ldmatrix lane base: lanes 0-7 rows r, 8-15 rows r+8, 16-23 (r, col+4), 24-31 (r+8, col+4)
    const int lrow = (lane & 7) + ((lane >> 3) & 1) * 8;
    const int lcol = (lane >> 4) * 4;
    const uint32_t a_base = smem_u32(&As[0][wr * 64 + lrow][lcol]);

    prefetch(0, 0); CP_COMMIT();
    prefetch(1, 1); CP_COMMIT();
    prefetch(2, 2); CP_COMMIT();

    for (int s = 0; s < 24; s++) {
        const int cur = s & 3;
        CP_WAIT(2);
        __syncthreads();                   // all warps done with buffer (s-1)%4
        if (s < 21) prefetch(s + 3, (s + 3) & 3);
        CP_COMMIT();

        uint32_t af[4][4];
        #pragma unroll
        for (int mi = 0; mi < 4; mi++) {
            uint32_t addr = a_base + (uint32_t)(cur * 6144 + mi * 768);
            asm volatile("ldmatrix.sync.aligned.m8n8.x4.shared.b16 {%0,%1,%2,%3}, [%4];"
                         : "=r"(af[mi][0]), "=r"(af[mi][1]), "=r"(af[mi][2]), "=r"(af[mi][3])
                         : "r"(addr));
        }
        uint32_t bf[4][2];
        #pragma unroll
        for (int ni = 0; ni < 4; ni++) {
            int m = wc * 32 + ni * 8 + gid;
            bf[ni][0] = Bs[cur][tig][m];
            bf[ni][1] = Bs[cur][tig + 4][m];
        }
        #pragma unroll
        for (int mi = 0; mi < 4; mi++)
            #pragma unroll
            for (int ni = 0; ni < 4; ni++)
                mma_f16(acc[mi][ni], af[mi], bf[ni][0], bf[ni][1]);
    }

    // epilogue: add bias, direct float2 stores
    #pragma unroll
    for (int mi = 0; mi < 4; mi++) {
        int nlo = n0 + wr * 64 + mi * 16 + gid;
        float blo = gbias[nlo / GG];
        float bhi = gbias[(nlo + 8) / GG];
        float* rowlo = &g_y[(((size_t)(b * NCH + nlo)) << 15) + ms];
        float* rowhi = rowlo + ((size_t)8 << 15);
        #pragma unroll
        for (int ni = 0; ni < 4; ni++) {
            int m = wc * 32 + ni * 8 + tig * 2;
            float2 lo = make_float2(acc[mi][ni][0] + blo, acc[mi][ni][1] + blo);
            float2 hi = make_float2(acc[mi][ni][2] + bhi, acc[mi][ni][3] + bhi);
            *(float2*)(rowlo + m) = lo;
            *(float2*)(rowhi + m) = hi;
        }
    }
}

// ================= depthwise 3x3x3 conv + bias + leaky ReLU (f32x2) =========
// 2 h-outputs per thread: 12 halo-row loads serve 18 tap-row applications.
__global__ void __launch_bounds__(256)
conv_kernel(float* __restrict__ out, const float* __restrict__ tbias) {
    __shared__ float tile[10][34][34];
    __shared__ float2 tap2[27];
    __shared__ float sbias;

    const int ch = blockIdx.x >> 2;
    const int h0 = (blockIdx.x & 3) * 8;
    const int tid = threadIdx.x;

    const float* ybase = g_y + (size_t)ch * SS;
    if (tid < 27) {
        float t = g_TFB[(ch % NCH) * 27 + tid];
        tap2[tid] = make_float2(t, t);
    }
    if (tid == 27) sbias = tbias[0];

    {
        float4* tz = (float4*)&tile[0][0][0];
        for (int i = tid; i < 2890; i += 256) tz[i] = make_float4(0.f, 0.f, 0.f, 0.f);
    }
    __syncthreads();

    {
        const int ww = tid >> 3;
        const int dd0 = (tid & 7) << 2;
        #pragma unroll
        for (int hh = 0; hh < 10; hh++) {
            int gh = h0 + hh - 1;
            if (gh >= 0 && gh < 32) {
                float4 v = *(const float4*)&ybase[(gh * 32 + ww) * 32 + dd0];
                float* trow = &tile[hh][ww + 1][1 + dd0];
                trow[0] = v.x; trow[1] = v.y; trow[2] = v.z; trow[3] = v.w;
            }
        }
    }
    __syncthreads();

    float* obase = out + (size_t)ch * SS + (size_t)h0 * 1024;
    #pragma unroll 1
    for (int it = 0; it < 2; it++) {
        int q = tid + it * 256;            // 0..511
        int d0 = (q & 3) << 3;             // 0,8,16,24
        int w = (q >> 2) & 31;
        int h = (q >> 7) * 2;              // 0,2,4,6
        ull aA[4], aB[4];
        #pragma unroll
        for (int i = 0; i < 4; i++) { aA[i] = dup2(sbias); aB[i] = dup2(sbias); }

        #pragma unroll
        for (int ar = 0; ar < 4; ar++)
            #pragma unroll
            for (int bq = 0; bq < 3; bq++) {
                const float* rp = &tile[h + ar][w + bq][d0];
                float2 f0 = *(const float2*)(rp + 0);
                float2 f1 = *(const float2*)(rp + 2);
                float2 f2 = *(const float2*)(rp + 4);
                float2 f3 = *(const float2*)(rp + 6);
                float2 f4 = *(const float2*)(rp + 8);
                ull w0 = pk2(f0.x, f0.y), w1 = pk2(f1.x, f1.y), w2 = pk2(f2.x, f2.y);
                ull w3 = pk2(f3.x, f3.y), w4 = pk2(f4.x, f4.y);
                ull s0 = pk2(f0.y, f1.x), s1 = pk2(f1.y, f2.x);
                ull s2 = pk2(f2.y, f3.x), s3 = pk2(f3.y, f4.x);
                if (ar < 3) {                      // contributes to output h (tap row ar)
                    const ull* tp = (const ull*)&tap2[ar * 9 + bq * 3];
                    ull t0 = tp[0], t1 = tp[1], t2 = tp[2];
                    aA[0] = ffma2(t0, w0, aA[0]); aA[0] = ffma2(t1, s0, aA[0]); aA[0] = ffma2(t2, w1, aA[0]);
                    aA[1] = ffma2(t0, w1, aA[1]); aA[1] = ffma2(t1, s1, aA[1]); aA[1] = ffma2(t2, w2, aA[1]);
                    aA[2] = ffma2(t0, w2, aA[2]); aA[2] = ffma2(t1, s2, aA[2]); aA[2] = ffma2(t2, w3, aA[2]);
                    aA[3] = ffma2(t0, w3, aA[3]); aA[3] = ffma2(t1, s3, aA[3]); aA[3] = ffma2(t2, w4, aA[3]);
                }
                if (ar > 0) {                      // contributes to output h+1 (tap row ar-1)
                    const ull* tp = (const ull*)&tap2[(ar - 1) * 9 + bq * 3];
                    ull t0 = tp[0], t1 = tp[1], t2 = tp[2];
                    aB[0] = ffma2(t0, w0, aB[0]); aB[0] = ffma2(t1, s0, aB[0]); aB[0] = ffma2(t2, w1, aB[0]);
                    aB[1] = ffma2(t0, w1, aB[1]); aB[1] = ffma2(t1, s1, aB[1]); aB[1] = ffma2(t2, w2, aB[1]);
                    aB[2] = ffma2(t0, w2, aB[2]); aB[2] = ffma2(t1, s2, aB[2]); aB[2] = ffma2(t2, w3, aB[2]);
                    aB[3] = ffma2(t0, w3, aB[3]); aB[3] = ffma2(t1, s3, aB[3]); aB[3] = ffma2(t2, w4, aB[3]);
                }
            }

        #pragma unroll
        for (int hh = 0; hh < 2; hh++) {
            const ull* A = hh ? aB : aA;
            float2 u0 = unpack2(A[0]), u1 = unpack2(A[1]), u2 = unpack2(A[2]), u3 = unpack2(A[3]);
            float4 o0, o1;
            o0.x = u0.x > 0.0f ? u0.x : 0.01f * u0.x;
            o0.y = u0.y > 0.0f ? u0.y : 0.01f * u0.y;
            o0.z = u1.x > 0.0f ? u1.x : 0.01f * u1.x;
            o0.w = u1.y > 0.0f ? u1.y : 0.01f * u1.y;
            o1.x = u2.x > 0.0f ? u2.x : 0.01f * u2.x;
            o1.y = u2.y > 0.0f ? u2.y : 0.01f * u2.y;
            o1.z = u3.x > 0.0f ? u3.x : 0.01f * u3.x;
            o1.w = u3.y > 0.0f ? u3.y : 0.01f * u3.y;
            float* dst = obase + (((h + hh) * 32 + w) * 32 + d0);
            *(float4*)dst = o0;
            *(float4*)(dst + 4) = o1;
        }
    }
}

// ---------------- launch ----------------
extern "C" void kernel_launch(void* const* d_in, const int* in_sizes, int n_in,
                              void* d_out, int out_size) {
    const float* x  = (const float*)d_in[0];
    const float* gw = (const float*)d_in[1];
    const float* tw = (const float*)d_in[2];
    const float* gb = (const float*)d_in[3];
    const float* tb = (const float*)d_in[4];
    float* out = (float*)d_out;

    build_tables_kernel<<<1, 648>>>();
    build_wh_kernel<<<(NCH * K2 + 255) / 256, 256>>>(gw);
    build_tfb_kernel<<<(NCH * 27 + 255) / 256, 256>>>(tw);
    convert_x_kernel<<<BB * K2 * 8192 / 256, 256>>>(x);

    dim3 gg(3, 512);
    gemm_mma_kernel<<<gg, 256>>>(gb);
    conv_kernel<<<3072, 256>>>(out, tb);
}

// round 9
// speedup vs baseline: 5.4801x; 1.0287x over previous
#include <cuda_runtime.h>
#include <cuda_fp16.h>
#include <cstdint>

using ull = unsigned long long;

#define GG 24
#define II 16
#define OO 16
#define SS 32768            // 32*32*32 spatial
#define NCH 384             // I*G == O*G
#define K2  192             // NCH/2 (fp16 k-pairs)
#define BB 2

// ---------------- device scratch (no allocations allowed) ----------------
__device__ int      g_shift[GG][GG];
__device__ int      g_rot[GG][27];
__device__ uint32_t g_Wh[NCH * K2];          // W^T[n][k-pair] packed f16x2
__device__ uint32_t g_xh[BB * K2 * SS];      // x[b][k-pair][m] packed f16x2 (50 MB)
__device__ float    g_TFB[NCH * 27];         // rotated depthwise taps per (o,z)
__device__ uint32_t g_yh[BB * NCH * (SS/2)]; // y packed f16x2 along m (50 MB)

__device__ __forceinline__ uint32_t smem_u32(const void* p) {
    uint32_t a;
    asm("{ .reg .u64 t; cvta.to.shared.u64 t, %1; cvt.u32.u64 %0, t; }" : "=r"(a) : "l"(p));
    return a;
}
__device__ __forceinline__ void mma_f16(float* c, const uint32_t* a, uint32_t b0, uint32_t b1) {
    asm volatile(
        "mma.sync.aligned.m16n8k16.row.col.f32.f16.f16.f32 "
        "{%0,%1,%2,%3}, {%4,%5,%6,%7}, {%8,%9}, {%0,%1,%2,%3};"
        : "+f"(c[0]), "+f"(c[1]), "+f"(c[2]), "+f"(c[3])
        : "r"(a[0]), "r"(a[1]), "r"(a[2]), "r"(a[3]), "r"(b0), "r"(b1));
}
__device__ __forceinline__ void cpasync16(uint32_t dst, const void* src) {
    asm volatile("cp.async.cg.shared.global [%0], [%1], 16;" :: "r"(dst), "l"(src));
}
#define CP_COMMIT() asm volatile("cp.async.commit_group;" ::: "memory")
#define CP_WAIT(n)  asm volatile("cp.async.wait_group %0;" :: "n"(n) : "memory")

__device__ __forceinline__ uint32_t packh2(float lo, float hi) {
    __half2 h = __halves2half2(__float2half(lo), __float2half(hi));
    return *reinterpret_cast<uint32_t*>(&h);
}
__device__ __forceinline__ float2 h2f2(uint32_t u) {
    return __half22float2(*reinterpret_cast<__half2*>(&u));
}

// ---- packed f32x2 helpers (conv) ----
__device__ __forceinline__ ull ffma2(ull a, ull b, ull c) {
    ull d;
    asm("fma.rn.f32x2 %0, %1, %2, %3;" : "=l"(d) : "l"(a), "l"(b), "l"(c));
    return d;
}
__device__ __forceinline__ ull dup2(float f) {
    ull d;
    asm("mov.b64 %0, {%1, %1};" : "=l"(d) : "f"(f));
    return d;
}
__device__ __forceinline__ ull pk2(float lo, float hi) {
    ull d;
    asm("mov.b64 %0, {%1, %2};" : "=l"(d) : "f"(lo), "f"(hi));
    return d;
}
__device__ __forceinline__ float2 unpack2(ull u) {
    float2 r;
    asm("mov.b64 {%0, %1}, %2;" : "=f"(r.x), "=f"(r.y) : "l"(u));
    return r;
}

// ---------------- table construction (replicates numpy enumeration) -----
__global__ void build_tables_kernel() {
    __shared__ int mats[24][9];
    int tid = threadIdx.x;
    if (tid == 0) {
        const int perms[6][3] = {{0,1,2},{0,2,1},{1,0,2},{1,2,0},{2,0,1},{2,1,0}};
        int cnt = 0;
        for (int p = 0; p < 6; p++)
            for (int sb = 0; sb < 8; sb++) {
                int s0 = (sb & 4) ? -1 : 1, s1 = (sb & 2) ? -1 : 1, s2 = (sb & 1) ? -1 : 1;
                int M[9] = {0,0,0,0,0,0,0,0,0};
                M[0*3 + perms[p][0]] = s0;
                M[1*3 + perms[p][1]] = s1;
                M[2*3 + perms[p][2]] = s2;
                int det = M[0]*(M[4]*M[8]-M[5]*M[7]) - M[1]*(M[3]*M[8]-M[5]*M[6]) + M[2]*(M[3]*M[7]-M[4]*M[6]);
                if (det == 1) { for (int q = 0; q < 9; q++) mats[cnt][q] = M[q]; cnt++; }
            }
    }
    __syncthreads();
    if (tid < 576) {                       // shift[g][h] = idx(Rg^T * Rh)
        int g = tid / 24, h = tid % 24;
        int R[9];
        for (int a = 0; a < 3; a++)
            for (int b = 0; b < 3; b++) {
                int v = 0;
                for (int c = 0; c < 3; c++) v += mats[g][c*3+a] * mats[h][c*3+b];
                R[a*3+b] = v;
            }
        int idx = 0;
        for (int j = 0; j < 24; j++) {
            bool eq = true;
            for (int q = 0; q < 9; q++) if (mats[j][q] != R[q]) { eq = false; break; }
            if (eq) { idx = j; break; }
        }
        g_shift[g][h] = idx;
    }
    if (tid < 648) {                       // rot_idx[g][j]
        int g = tid / 27, j = tid % 27;
        int x0 = j / 9 - 1, x1 = (j / 3) % 3 - 1, x2 = j % 3 - 1;
        int r0 = x0*mats[g][0] + x1*mats[g][3] + x2*mats[g][6] + 1;
        int r1 = x0*mats[g][1] + x1*mats[g][4] + x2*mats[g][7] + 1;
        int r2 = x0*mats[g][2] + x1*mats[g][5] + x2*mats[g][8] + 1;
        g_rot[g][j] = r0*9 + r1*3 + r2;
    }
}

// W^T[n][k2] = pack(W[2k2][n], W[2k2+1][n]) in fp16
__global__ void build_wh_kernel(const float* __restrict__ gw) {
    int idx = blockIdx.x * blockDim.x + threadIdx.x;
    if (idx >= NCH * K2) return;
    int n = idx / K2, k2 = idx % K2;
    int o = n / GG, z = n % GG;
    int k0 = 2 * k2, k1 = 2 * k2 + 1;
    int i0 = k0 / GG, gg0 = k0 % GG;
    int i1 = k1 / GG, gg1 = k1 % GG;
    float w0 = gw[(g_shift[z][gg0] * OO + o) * II + i0];
    float w1 = gw[(g_shift[z][gg1] * OO + o) * II + i1];
    g_Wh[idx] = packh2(w0, w1);
}

__global__ void build_tfb_kernel(const float* __restrict__ tw) {
    int idx = blockIdx.x * blockDim.x + threadIdx.x;
    if (idx >= NCH * 27) return;
    int n = idx / 27, j = idx % 27;
    g_TFB[idx] = tw[(n / GG) * 27 + g_rot[n % GG][j]];
}

// x -> fp16 k-pair packed
__global__ void __launch_bounds__(256)
convert_x_kernel(const float* __restrict__ x) {
    int idx = blockIdx.x * blockDim.x + threadIdx.x;
    int m4 = (idx & 8191) << 2;
    int k2 = (idx >> 13) % K2;
    int b  = idx / (K2 * 8192);
    const float* r0 = &x[(((size_t)(b * NCH + 2 * k2)) << 15) + m4];
    float4 a = *(const float4*)r0;
    float4 c = *(const float4*)(r0 + SS);
    uint4 o;
    o.x = packh2(a.x, c.x);
    o.y = packh2(a.y, c.y);
    o.z = packh2(a.z, c.z);
    o.w = packh2(a.w, c.w);
    *(uint4*)&g_xh[(((size_t)(b * K2 + k2)) << 15) + m4] = o;
}

// ================= fp16 mma.sync GEMM, cp.async 4-stage (k16) =================
// CTA 128n x 128m, 24 k-steps of 16; 8 warps (2 n-halves x 4 m-quarters).
// A frags via ldmatrix.x4 (pitch-12 conflict-free); epilogue stores fp16 y.
__global__ void __launch_bounds__(256, 2)
gemm_mma_kernel(const float* __restrict__ gbias) {
    __shared__ uint32_t As[4][128][12];
    __shared__ uint32_t Bs[4][8][136];

    const int tid  = threadIdx.x;
    const int lane = tid & 31;
    const int wid  = tid >> 5;
    const int wr   = wid >> 2;            // 0..1 : n 64-half
    const int wc   = wid & 3;             // 0..3 : m 32-quarter
    const int n0   = blockIdx.x * 128;    // 0,128,256
    const int m0   = blockIdx.y * 128;
    const int b    = m0 >> 15;
    const int ms   = m0 & (SS - 1);

    const int gid  = lane >> 2;           // 0..7
    const int tig  = lane & 3;            // 0..3

    float acc[4][4][4];
    #pragma unroll
    for (int i = 0; i < 4; i++)
        #pragma unroll
        for (int j = 0; j < 4; j++)
            #pragma unroll
            for (int q = 0; q < 4; q++) acc[i][j][q] = 0.0f;

    // cp.async slots
    const int arow = tid >> 1, ac = (tid & 1) << 2;      // A: [128 n][8 k2]
    const int brow = tid >> 5, bc = (tid & 31) << 2;     // B: [8 k2][128 m]
    const uint32_t* asrc_base = &g_Wh[(n0 + arow) * K2 + ac];
    const uint32_t* bsrc_base = &g_xh[(((size_t)(b * K2 + brow)) << 15) + ms + bc];

    auto prefetch = [&](int ks, int s) {
        const int k20 = ks * 8;
        cpasync16(smem_u32(&As[s][arow][ac]), asrc_base + k20);
        cpasync16(smem_u32(&Bs[s][brow][bc]), bsrc_base + ((size_t)k20 << 15));
    };

    const int lrow = (lane & 7) + ((lane >> 3) & 1) * 8;
    const int lcol = (lane >> 4) * 4;
    const uint32_t a_base = smem_u32(&As[0][wr * 64 + lrow][lcol]);

    prefetch(0, 0); CP_COMMIT();
    prefetch(1, 1); CP_COMMIT();
    prefetch(2, 2); CP_COMMIT();

    for (int s = 0; s < 24; s++) {
        const int cur = s & 3;
        CP_WAIT(2);
        __syncthreads();
        if (s < 21) prefetch(s + 3, (s + 3) & 3);
        CP_COMMIT();

        uint32_t af[4][4];
        #pragma unroll
        for (int mi = 0; mi < 4; mi++) {
            uint32_t addr = a_base + (uint32_t)(cur * 6144 + mi * 768);
            asm volatile("ldmatrix.sync.aligned.m8n8.x4.shared.b16 {%0,%1,%2,%3}, [%4];"
                         : "=r"(af[mi][0]), "=r"(af[mi][1]), "=r"(af[mi][2]), "=r"(af[mi][3])
                         : "r"(addr));
        }
        uint32_t bf[4][2];
        #pragma unroll
        for (int ni = 0; ni < 4; ni++) {
            int m = wc * 32 + ni * 8 + gid;
            bf[ni][0] = Bs[cur][tig][m];
            bf[ni][1] = Bs[cur][tig + 4][m];
        }
        #pragma unroll
        for (int mi = 0; mi < 4; mi++)
            #pragma unroll
            for (int ni = 0; ni < 4; ni++)
                mma_f16(acc[mi][ni], af[mi], bf[ni][0], bf[ni][1]);
    }

    // epilogue: add bias, pack fp16 m-pairs, store u32
    #pragma unroll
    for (int mi = 0; mi < 4; mi++) {
        int nlo = n0 + wr * 64 + mi * 16 + gid;
        float blo = gbias[nlo / GG];
        float bhi = gbias[(nlo + 8) / GG];
        uint32_t* rowlo = &g_yh[(((size_t)(b * NCH + nlo)) << 14) + (ms >> 1)];
        uint32_t* rowhi = rowlo + ((size_t)8 << 14);
        #pragma unroll
        for (int ni = 0; ni < 4; ni++) {
            int m = wc * 32 + ni * 8 + tig * 2;
            rowlo[m >> 1] = packh2(acc[mi][ni][0] + blo, acc[mi][ni][1] + blo);
            rowhi[m >> 1] = packh2(acc[mi][ni][2] + bhi, acc[mi][ni][3] + bhi);
        }
    }
}

// ================= depthwise 3x3x3 conv + bias + leaky ReLU (f32x2) =========
// y read as fp16 pairs, expanded to fp32 smem tile; 2 h-outputs per thread.
__global__ void __launch_bounds__(256)
conv_kernel(float* __restrict__ out, const float* __restrict__ tbias) {
    __shared__ float tile[10][34][34];
    __shared__ float2 tap2[27];
    __shared__ float sbias;

    const int ch = blockIdx.x >> 2;
    const int h0 = (blockIdx.x & 3) * 8;
    const int tid = threadIdx.x;

    const uint32_t* ybase = g_yh + ((size_t)ch << 14);
    if (tid < 27) {
        float t = g_TFB[(ch % NCH) * 27 + tid];
        tap2[tid] = make_float2(t, t);
    }
    if (tid == 27) sbias = tbias[0];

    {
        float4* tz = (float4*)&tile[0][0][0];
        for (int i = tid; i < 2890; i += 256) tz[i] = make_float4(0.f, 0.f, 0.f, 0.f);
    }
    __syncthreads();

    {
        const int ww = tid >> 3;
        const int dd0 = (tid & 7) << 2;
        #pragma unroll
        for (int hh = 0; hh < 10; hh++) {
            int gh = h0 + hh - 1;
            if (gh >= 0 && gh < 32) {
                uint2 v = *(const uint2*)&ybase[(gh * 32 + ww) * 16 + (dd0 >> 1)];
                float2 p0 = h2f2(v.x);
                float2 p1 = h2f2(v.y);
                float* trow = &tile[hh][ww + 1][1 + dd0];
                trow[0] = p0.x; trow[1] = p0.y; trow[2] = p1.x; trow[3] = p1.y;
            }
        }
    }
    __syncthreads();

    float* obase = out + (size_t)ch * SS + (size_t)h0 * 1024;
    #pragma unroll 1
    for (int it = 0; it < 2; it++) {
        int q = tid + it * 256;            // 0..511
        int d0 = (q & 3) << 3;             // 0,8,16,24
        int w = (q >> 2) & 31;
        int h = (q >> 7) * 2;              // 0,2,4,6
        ull aA[4], aB[4];
        #pragma unroll
        for (int i = 0; i < 4; i++) { aA[i] = dup2(sbias); aB[i] = dup2(sbias); }

        #pragma unroll
        for (int ar = 0; ar < 4; ar++)
            #pragma unroll
            for (int bq = 0; bq < 3; bq++) {
                const float* rp = &tile[h + ar][w + bq][d0];
                float2 f0 = *(const float2*)(rp + 0);
                float2 f1 = *(const float2*)(rp + 2);
                float2 f2 = *(const float2*)(rp + 4);
                float2 f3 = *(const float2*)(rp + 6);
                float2 f4 = *(const float2*)(rp + 8);
                ull w0 = pk2(f0.x, f0.y), w1 = pk2(f1.x, f1.y), w2 = pk2(f2.x, f2.y);
                ull w3 = pk2(f3.x, f3.y), w4 = pk2(f4.x, f4.y);
                ull s0 = pk2(f0.y, f1.x), s1 = pk2(f1.y, f2.x);
                ull s2 = pk2(f2.y, f3.x), s3 = pk2(f3.y, f4.x);
                if (ar < 3) {
                    const ull* tp = (const ull*)&tap2[ar * 9 + bq * 3];
                    ull t0 = tp[0], t1 = tp[1], t2 = tp[2];
                    aA[0] = ffma2(t0, w0, aA[0]); aA[0] = ffma2(t1, s0, aA[0]); aA[0] = ffma2(t2, w1, aA[0]);
                    aA[1] = ffma2(t0, w1, aA[1]); aA[1] = ffma2(t1, s1, aA[1]); aA[1] = ffma2(t2, w2, aA[1]);
                    aA[2] = ffma2(t0, w2, aA[2]); aA[2] = ffma2(t1, s2, aA[2]); aA[2] = ffma2(t2, w3, aA[2]);
                    aA[3] = ffma2(t0, w3, aA[3]); aA[3] = ffma2(t1, s3, aA[3]); aA[3] = ffma2(t2, w4, aA[3]);
                }
                if (ar > 0) {
                    const ull* tp = (const ull*)&tap2[(ar - 1) * 9 + bq * 3];
                    ull t0 = tp[0], t1 = tp[1], t2 = tp[2];
                    aB[0] = ffma2(t0, w0, aB[0]); aB[0] = ffma2(t1, s0, aB[0]); aB[0] = ffma2(t2, w1, aB[0]);
                    aB[1] = ffma2(t0, w1, aB[1]); aB[1] = ffma2(t1, s1, aB[1]); aB[1] = ffma2(t2, w2, aB[1]);
                    aB[2] = ffma2(t0, w2, aB[2]); aB[2] = ffma2(t1, s2, aB[2]); aB[2] = ffma2(t2, w3, aB[2]);
                    aB[3] = ffma2(t0, w3, aB[3]); aB[3] = ffma2(t1, s3, aB[3]); aB[3] = ffma2(t2, w4, aB[3]);
                }
            }

        #pragma unroll
        for (int hh = 0; hh < 2; hh++) {
            const ull* A = hh ? aB : aA;
            float2 u0 = unpack2(A[0]), u1 = unpack2(A[1]), u2 = unpack2(A[2]), u3 = unpack2(A[3]);
            float4 o0, o1;
            o0.x = u0.x > 0.0f ? u0.x : 0.01f * u0.x;
            o0.y = u0.y > 0.0f ? u0.y : 0.01f * u0.y;
            o0.z = u1.x > 0.0f ? u1.x : 0.01f * u1.x;
            o0.w = u1.y > 0.0f ? u1.y : 0.01f * u1.y;
            o1.x = u2.x > 0.0f ? u2.x : 0.01f * u2.x;
            o1.y = u2.y > 0.0f ? u2.y : 0.01f * u2.y;
            o1.z = u3.x > 0.0f ? u3.x : 0.01f * u3.x;
            o1.w = u3.y > 0.0f ? u3.y : 0.01f * u3.y;
            float* dst = obase + (((h + hh) * 32 + w) * 32 + d0);
            *(float4*)dst = o0;
            *(float4*)(dst + 4) = o1;
        }
    }
}

// ---------------- launch ----------------
extern "C" void kernel_launch(void* const* d_in, const int* in_sizes, int n_in,
                              void* d_out, int out_size) {
    const float* x  = (const float*)d_in[0];
    const float* gw = (const float*)d_in[1];
    const float* tw = (const float*)d_in[2];
    const float* gb = (const float*)d_in[3];
    const float* tb = (const float*)d_in[4];
    float* out = (float*)d_out;

    build_tables_kernel<<<1, 648>>>();
    build_wh_kernel<<<(NCH * K2 + 255) / 256, 256>>>(gw);
    build_tfb_kernel<<<(NCH * 27 + 255) / 256, 256>>>(tw);
    convert_x_kernel<<<BB * K2 * 8192 / 256, 256>>>(x);

    dim3 gg(3, 512);
    gemm_mma_kernel<<<gg, 256>>>(gb);
    conv_kernel<<<3072, 256>>>(out, tb);
}